// round 6
// baseline (speedup 1.0000x reference)
#include <cuda_runtime.h>
#include <cstdint>

typedef unsigned long long ull;

// Problem constants
#define BATCH 16
#define NPER  1310720          // 256*256*20 elements per batch row
#define N4    (NPER/4)         // 327680 float4 per batch
#define T1    256              // threads per block

// fused pass geometry
#define BPB   256              // blocks per batch
#define F4B   (N4/BPB)         // 1280 float4 per block
#define ITF   (F4B/T1)         // 5 iterations per block
#define STAGE_CAP (ITF*T1*4)   // 5120 floats: block can stage ALL its elements

// sample (histogram) pass geometry: 1/8 systematic sample
#define HBPB    80             // blocks per batch
#define HSTRIDE (N4/HBPB)      // 4096 float4 stripe per block
#define HF4     512            // float4 actually read per block (2 iters)
#define SCALE   8              // inverse sample fraction
#define NBINS   512            // coarse bins: float bits >> 22

#define CAP2  NPER             // per-batch survivor capacity (cannot overflow)

// ---------------- packed f32x2 helpers -------------------------------------
__device__ __forceinline__ ull pk2(float lo, float hi) {
    ull r; asm("mov.b64 %0,{%1,%2};" : "=l"(r) : "f"(lo), "f"(hi)); return r;
}
__device__ __forceinline__ void up2(ull v, float& lo, float& hi) {
    asm("mov.b64 {%0,%1},%2;" : "=f"(lo), "=f"(hi) : "l"(v));
}
__device__ __forceinline__ ull fma2(ull a, ull b, ull c) {
    ull r; asm("fma.rn.f32x2 %0,%1,%2,%3;" : "=l"(r) : "l"(a), "l"(b), "l"(c)); return r;
}
__device__ __forceinline__ ull mul2(ull a, ull b) {
    ull r; asm("mul.rn.f32x2 %0,%1,%2;" : "=l"(r) : "l"(a), "l"(b)); return r;
}
__device__ __forceinline__ ull add2(ull a, ull b) {
    ull r; asm("add.rn.f32x2 %0,%1,%2;" : "=l"(r) : "l"(a), "l"(b)); return r;
}

// ---------------- static device scratch ------------------------------------
__device__ float    g_cand2[(size_t)BATCH * CAP2];   // survivors (>= t0)
__device__ unsigned g_hist [BATCH * NBINS];          // sampled histogram
__device__ unsigned g_cnt2 [BATCH];
__device__ double   g_psum [BATCH];
__device__ double   g_msum;
__device__ double   g_train;
__device__ float    g_t0   [BATCH];
__device__ int      g_k    [BATCH];
__device__ int      g_redo [BATCH];

// ---------------- K0: zero scratch -----------------------------------------
__global__ void k_zero() {
    int i = blockIdx.x * blockDim.x + threadIdx.x;
    if (i < BATCH * NBINS) g_hist[i] = 0u;
    if (i < BATCH) { g_cnt2[i] = 0u; g_psum[i] = 0.0; g_redo[i] = 0; }
    if (i == 0)   { g_msum = 0.0; g_train = 0.0; }
}

// ---------------- K1: sampled histogram (reads 1/8 of inputs) --------------
__global__ __launch_bounds__(T1) void k_hist(const float4* __restrict__ y,
                                             const float4* __restrict__ o,
                                             const float4* __restrict__ w) {
    __shared__ unsigned hist[8][NBINS];
    const int tid  = threadIdx.x;
    const int warp = tid >> 5;

    for (int i = tid; i < 8 * NBINS; i += T1) (&hist[0][0])[i] = 0u;
    __syncthreads();

    const int b = blockIdx.x / HBPB;
    const int j = blockIdx.x % HBPB;
    const size_t base = (size_t)b * N4 + (size_t)j * HSTRIDE;
    unsigned* myh = hist[warp];

#pragma unroll
    for (int it = 0; it < HF4 / T1; ++it) {       // 2 iterations
        const size_t idx = base + (size_t)it * T1 + tid;
        const float4 yv = y[idx];
        const float4 ov = o[idx];
        const float4 wv = w[idx];
#define HPROC(c)                                                            \
        {                                                                   \
            float d = ov.c - yv.c;  float m = d * d;                        \
            if (ov.c > 0.0f && wv.c == 0.0f)                                \
                atomicAdd(&myh[__float_as_uint(m) >> 22], 1u);              \
        }
        HPROC(x) HPROC(y) HPROC(z) HPROC(w)
#undef HPROC
    }
    __syncthreads();
    for (int bin = tid; bin < NBINS; bin += T1) {
        unsigned s = 0;
#pragma unroll
        for (int wp = 0; wp < 8; wp++) s += hist[wp][bin];
        if (s) atomicAdd(&g_hist[b * NBINS + bin], s);
    }
}

// ---------------- K2: conservative threshold from sampled hist -------------
__global__ void k_sel(const float* __restrict__ ts) {
    int b = threadIdx.x;
    if (b >= BATCH) return;
    long long K = (long long)((int)ts[b]) * 3;     // NEG_POS_RATIO
    if (K > NPER) K = NPER;
    if (K < 0)    K = 0;
    g_k[b] = (int)K;

    if (K == 0) { g_t0[b] = 3.4e38f; return; }

    const long long target = 2 * K + 64;           // 2x margin + slack
    unsigned long long acc = 0;
    int bstar = 0;
    for (int bin = NBINS - 1; bin >= 1; --bin) {
        acc += g_hist[b * NBINS + bin];
        if ((long long)(acc * SCALE) >= target) { bstar = bin; break; }
    }
    g_t0[b] = (bstar == 0) ? 1.4e-45f : __uint_as_float((unsigned)bstar << 22);
}

// ---------------- K3: fused main pass: sums + direct compaction ------------
__global__ __launch_bounds__(T1) void k_fused(const float4* __restrict__ y,
                                              const float4* __restrict__ o,
                                              const float4* __restrict__ w) {
    __shared__ float    stage[STAGE_CAP];
    __shared__ unsigned s_cnt, s_base;
    __shared__ float    rm[8], rp[8];

    const int tid  = threadIdx.x;
    const int warp = tid >> 5;
    const int lane = tid & 31;
    if (tid == 0) s_cnt = 0u;
    __syncthreads();

    const int b     = blockIdx.x / BPB;
    const int chunk = blockIdx.x % BPB;
    const size_t base = (size_t)b * N4 + (size_t)chunk * F4B;
    const float t0 = g_t0[b];

    const ull NEG1 = pk2(-1.0f, -1.0f);
    ull msA = 0ull, msB = 0ull, psA = 0ull, psB = 0ull;   // packed {0,0}

#pragma unroll
    for (int it = 0; it < ITF; ++it) {
        const size_t idx = base + (size_t)it * T1 + tid;
        const float4 yv = y[idx];
        const float4 ov = o[idx];
        const float4 wv = w[idx];

        const ull y01 = pk2(yv.x, yv.y), y23 = pk2(yv.z, yv.w);
        const ull o01 = pk2(ov.x, ov.y), o23 = pk2(ov.z, ov.w);
        const ull w01 = pk2(wv.x, wv.y), w23 = pk2(wv.z, wv.w);

        const ull d01 = fma2(y01, NEG1, o01);      // o - y (exact, same as sub)
        const ull d23 = fma2(y23, NEG1, o23);
        const ull m01 = mul2(d01, d01);
        const ull m23 = mul2(d23, d23);
        msA = add2(msA, m01);  msB = add2(msB, m23);
        psA = fma2(w01, m01, psA);  psB = fma2(w23, m23, psB);

        float m0, m1, m2, m3;
        up2(m01, m0, m1);  up2(m23, m2, m3);

        // cheap OR-chain guard; full predicate only on the rare path (~4%/float4)
        if (m0 >= t0 || m1 >= t0 || m2 >= t0 || m3 >= t0) {
            if (m0 >= t0 && ov.x > 0.0f && wv.x == 0.0f) stage[atomicAdd(&s_cnt, 1u)] = m0;
            if (m1 >= t0 && ov.y > 0.0f && wv.y == 0.0f) stage[atomicAdd(&s_cnt, 1u)] = m1;
            if (m2 >= t0 && ov.z > 0.0f && wv.z == 0.0f) stage[atomicAdd(&s_cnt, 1u)] = m2;
            if (m3 >= t0 && ov.w > 0.0f && wv.w == 0.0f) stage[atomicAdd(&s_cnt, 1u)] = m3;
        }
    }

    // reduce msum / psum
    float a0, a1, b0, b1, c0, c1, e0, e1;
    up2(msA, a0, a1); up2(msB, b0, b1);
    up2(psA, c0, c1); up2(psB, e0, e1);
    float msum = (a0 + a1) + (b0 + b1);
    float psum = (c0 + c1) + (e0 + e1);
    for (int off = 16; off; off >>= 1) {
        msum += __shfl_down_sync(0xffffffffu, msum, off);
        psum += __shfl_down_sync(0xffffffffu, psum, off);
    }
    if (lane == 0) { rm[warp] = msum; rp[warp] = psum; }
    __syncthreads();                                  // also orders all stage writes
    if (tid == 0) {
        double mm = 0.0, pp = 0.0;
#pragma unroll
        for (int i = 0; i < 8; i++) { mm += (double)rm[i]; pp += (double)rp[i]; }
        atomicAdd(&g_msum, mm);
        atomicAdd(&g_psum[b], pp);
    }

    // single end-of-kernel flush of staged survivors
    const unsigned c = s_cnt;
    if (tid == 0 && c) s_base = atomicAdd(&g_cnt2[b], c);
    __syncthreads();
    if (c) {
        float* outp = g_cand2 + (size_t)b * CAP2 + s_base;
        for (unsigned i = tid; i < c; i += T1) outp[i] = stage[i];
    }
}

// ---------------- K4: verify survivor count; arm fallback ------------------
__global__ void k_check() {
    int b = threadIdx.x;
    if (b >= BATCH) return;
    if (g_cnt2[b] < (unsigned)g_k[b]) {      // threshold missed -> take all positives
        g_redo[b] = 1;
        g_cnt2[b] = 0u;
        g_t0[b]   = 1.4e-45f;
    }
}

// ---------------- K5: fallback refilter from inputs (no-op unless armed) ---
__global__ __launch_bounds__(T1) void k_fb(const float4* __restrict__ y,
                                           const float4* __restrict__ o,
                                           const float4* __restrict__ w) {
    const int b = blockIdx.x / BPB;
    if (!g_redo[b]) return;

    __shared__ float    stage[STAGE_CAP];
    __shared__ unsigned s_cnt, s_base;
    const int tid = threadIdx.x;
    if (tid == 0) s_cnt = 0u;
    __syncthreads();

    const int chunk = blockIdx.x % BPB;
    const size_t base = (size_t)b * N4 + (size_t)chunk * F4B;
    const float t0 = g_t0[b];

#pragma unroll
    for (int it = 0; it < ITF; ++it) {
        const size_t idx = base + (size_t)it * T1 + tid;
        const float4 yv = y[idx];
        const float4 ov = o[idx];
        const float4 wv = w[idx];
#define FPROC(c)                                                            \
        {                                                                   \
            float d = ov.c - yv.c;  float m = d * d;                        \
            if (m >= t0 && ov.c > 0.0f && wv.c == 0.0f)                     \
                stage[atomicAdd(&s_cnt, 1u)] = m;                           \
        }
        FPROC(x) FPROC(y) FPROC(z) FPROC(w)
#undef FPROC
    }
    __syncthreads();
    const unsigned c = s_cnt;
    if (tid == 0 && c) s_base = atomicAdd(&g_cnt2[b], c);
    __syncthreads();
    if (c) {
        float* outp = g_cand2 + (size_t)b * CAP2 + s_base;
        for (unsigned i = tid; i < c; i += T1) outp[i] = stage[i];
    }
}

// ---------------- K6: exact top-k sum: counts-only radix + sum pass --------
__global__ __launch_bounds__(T1) void k_topk(const float* __restrict__ ts) {
    const int b    = blockIdx.x;
    const int tid  = threadIdx.x;
    const int lane = tid & 31;

    __shared__ unsigned cnt[256];
    __shared__ unsigned sh_prefix;
    __shared__ int      sh_krem;
    __shared__ double   red[8];

    const float* vals = g_cand2 + (size_t)b * CAP2;
    const unsigned c  = g_cnt2[b];
    const int K = g_k[b];

    double negsum = 0.0;

    if (c <= (unsigned)K) {
        float acc = 0.f;
        for (unsigned i = tid; i < c; i += T1) acc += vals[i];
        for (int off = 16; off; off >>= 1) acc += __shfl_down_sync(0xffffffffu, acc, off);
        if (lane == 0) red[tid >> 5] = (double)acc;
        __syncthreads();
        if (tid == 0) {
#pragma unroll
            for (int i = 0; i < 8; i++) negsum += red[i];
        }
    } else {
        if (tid == 0) { sh_prefix = 0u; sh_krem = K; }
        const unsigned cpad = ((c + T1 - 1) / T1) * T1;   // all lanes reach collectives
        for (int r = 0; r < 4; ++r) {
            cnt[tid] = 0u;
            __syncthreads();
            const unsigned pfx = sh_prefix;
            const int shift = 24 - 8 * r;
            for (unsigned i = tid; i < cpad; i += T1) {
                const bool valid = (i < c);
                const unsigned u = valid ? __float_as_uint(vals[i]) : 0u;
                const bool match = valid && ((r == 0) || ((u >> (32 - 8 * r)) == pfx));
                const unsigned bin = (u >> shift) & 255u;
                const unsigned act = __ballot_sync(0xffffffffu, match);
                if (match) {
                    const unsigned peers = __match_any_sync(act, bin);
                    if (lane == (__ffs(peers) - 1))
                        atomicAdd(&cnt[bin], (unsigned)__popc(peers));
                }
            }
            __syncthreads();
            if (tid == 0) {
                int krem = sh_krem;
                int chosen = 0;
                for (int bin = 255; bin >= 0; --bin) {
                    if ((unsigned)krem <= cnt[bin]) { chosen = bin; break; }
                    krem -= (int)cnt[bin];
                }
                sh_prefix = (sh_prefix << 8) | (unsigned)chosen;
                sh_krem = krem;
            }
            __syncthreads();
        }
        const unsigned thr = sh_prefix;
        float acc = 0.f;
        for (unsigned i = tid; i < c; i += T1) {
            const float v = vals[i];
            if (__float_as_uint(v) > thr) acc += v;
        }
        for (int off = 16; off; off >>= 1) acc += __shfl_down_sync(0xffffffffu, acc, off);
        if (lane == 0) red[tid >> 5] = (double)acc;
        __syncthreads();
        if (tid == 0) {
#pragma unroll
            for (int i = 0; i < 8; i++) negsum += red[i];
            negsum += (double)sh_krem * (double)__uint_as_float(thr);  // ties
        }
    }

    if (tid == 0) {
        const float t = ts[b];
        const double per = (t > 0.f)
            ? (g_psum[b] + negsum) / (double)t     // ALPHA = 1
            : 0.0;
        atomicAdd(&g_train, per);
    }
}

// ---------------- K7: final scalar -----------------------------------------
__global__ void k_final(float* __restrict__ outp) {
    const double train = g_train / (double)BATCH;
    const double mmean = g_msum / ((double)BATCH * (double)NPER);
    outp[0] = (float)((train + mmean) * 10.0);
}

// ---------------- launch ----------------------------------------------------
extern "C" void kernel_launch(void* const* d_in, const int* in_sizes, int n_in,
                              void* d_out, int out_size) {
    const float4* y  = (const float4*)d_in[0];
    const float4* o  = (const float4*)d_in[1];
    const float4* w  = (const float4*)d_in[2];
    const float*  ts = (const float*)d_in[3];

    k_zero  <<<(BATCH * NBINS + T1 - 1) / T1, T1>>>();
    k_hist  <<<BATCH * HBPB, T1>>>(y, o, w);
    k_sel   <<<1, 32>>>(ts);
    k_fused <<<BATCH * BPB, T1>>>(y, o, w);
    k_check <<<1, 32>>>();
    k_fb    <<<BATCH * BPB, T1>>>(y, o, w);
    k_topk  <<<BATCH, T1>>>(ts);
    k_final <<<1, 1>>>((float*)d_out);
}

// round 7
// speedup vs baseline: 2.1034x; 2.1034x over previous
#include <cuda_runtime.h>
#include <cstdint>

typedef unsigned long long ull;

// Problem constants
#define BATCH 16
#define NPER  1310720          // 256*256*20 elements per batch row
#define N4    (NPER/4)         // 327680 float4 per batch
#define T1    256              // threads per block (big passes)
#define T2    1024             // threads per block (top-k)

// fused pass geometry
#define BPB   256              // blocks per batch
#define F4B   (N4/BPB)         // 1280 float4 per block
#define ITF   (F4B/T1)         // 5 iterations per block
#define STAGE_CAP (ITF*T1*4)   // 5120 floats: block can stage ALL its elements

// sample (histogram) pass geometry: 1/8 systematic sample
#define HBPB    80             // blocks per batch
#define HSTRIDE (N4/HBPB)      // 4096 float4 stripe per block
#define HF4     512            // float4 actually read per block (2 iters)
#define SCALE   8              // inverse sample fraction
#define NBINS   512            // coarse bins: float bits >> 22

#define CAP2  NPER             // per-batch survivor capacity (cannot overflow)

// ---------------- packed f32x2 helpers -------------------------------------
__device__ __forceinline__ ull pk2(float lo, float hi) {
    ull r; asm("mov.b64 %0,{%1,%2};" : "=l"(r) : "f"(lo), "f"(hi)); return r;
}
__device__ __forceinline__ void up2(ull v, float& lo, float& hi) {
    asm("mov.b64 {%0,%1},%2;" : "=f"(lo), "=f"(hi) : "l"(v));
}
__device__ __forceinline__ ull fma2(ull a, ull b, ull c) {
    ull r; asm("fma.rn.f32x2 %0,%1,%2,%3;" : "=l"(r) : "l"(a), "l"(b), "l"(c)); return r;
}
__device__ __forceinline__ ull mul2(ull a, ull b) {
    ull r; asm("mul.rn.f32x2 %0,%1,%2;" : "=l"(r) : "l"(a), "l"(b)); return r;
}
__device__ __forceinline__ ull add2(ull a, ull b) {
    ull r; asm("add.rn.f32x2 %0,%1,%2;" : "=l"(r) : "l"(a), "l"(b)); return r;
}

// ---------------- static device scratch ------------------------------------
__device__ float    g_cand2[(size_t)BATCH * CAP2];   // survivors (>= t0)
__device__ unsigned g_hist [BATCH * NBINS];          // sampled histogram
__device__ unsigned g_cnt2 [BATCH];
__device__ double   g_psum [BATCH];
__device__ double   g_msum;
__device__ double   g_train;
__device__ float    g_t0   [BATCH];
__device__ int      g_k    [BATCH];
__device__ int      g_redo [BATCH];

// ---------------- K0: zero scratch -----------------------------------------
__global__ void k_zero() {
    int i = blockIdx.x * blockDim.x + threadIdx.x;
    if (i < BATCH * NBINS) g_hist[i] = 0u;
    if (i < BATCH) { g_cnt2[i] = 0u; g_psum[i] = 0.0; g_redo[i] = 0; }
    if (i == 0)   { g_msum = 0.0; g_train = 0.0; }
}

// ---------------- K1: sampled histogram (reads 1/8 of inputs) --------------
__global__ __launch_bounds__(T1) void k_hist(const float4* __restrict__ y,
                                             const float4* __restrict__ o,
                                             const float4* __restrict__ w) {
    __shared__ unsigned hist[8][NBINS];
    const int tid  = threadIdx.x;
    const int warp = tid >> 5;

    for (int i = tid; i < 8 * NBINS; i += T1) (&hist[0][0])[i] = 0u;
    __syncthreads();

    const int b = blockIdx.x / HBPB;
    const int j = blockIdx.x % HBPB;
    const size_t base = (size_t)b * N4 + (size_t)j * HSTRIDE;
    unsigned* myh = hist[warp];

#pragma unroll
    for (int it = 0; it < HF4 / T1; ++it) {       // 2 iterations
        const size_t idx = base + (size_t)it * T1 + tid;
        const float4 yv = y[idx];
        const float4 ov = o[idx];
        const float4 wv = w[idx];
#define HPROC(c)                                                            \
        {                                                                   \
            float d = ov.c - yv.c;  float m = d * d;                        \
            if (ov.c > 0.0f && wv.c == 0.0f)                                \
                atomicAdd(&myh[__float_as_uint(m) >> 22], 1u);              \
        }
        HPROC(x) HPROC(y) HPROC(z) HPROC(w)
#undef HPROC
    }
    __syncthreads();
    for (int bin = tid; bin < NBINS; bin += T1) {
        unsigned s = 0;
#pragma unroll
        for (int wp = 0; wp < 8; wp++) s += hist[wp][bin];
        if (s) atomicAdd(&g_hist[b * NBINS + bin], s);
    }
}

// ---------------- K2: conservative threshold from sampled hist -------------
__global__ void k_sel(const float* __restrict__ ts) {
    int b = threadIdx.x;
    if (b >= BATCH) return;
    long long K = (long long)((int)ts[b]) * 3;     // NEG_POS_RATIO
    if (K > NPER) K = NPER;
    if (K < 0)    K = 0;
    g_k[b] = (int)K;

    if (K == 0) { g_t0[b] = 3.4e38f; return; }

    const long long target = 2 * K + 64;           // 2x margin + slack
    unsigned long long acc = 0;
    int bstar = 0;
    for (int bin = NBINS - 1; bin >= 1; --bin) {
        acc += g_hist[b * NBINS + bin];
        if ((long long)(acc * SCALE) >= target) { bstar = bin; break; }
    }
    g_t0[b] = (bstar == 0) ? 1.4e-45f : __uint_as_float((unsigned)bstar << 22);
}

// ---------------- K3: fused main pass: sums + direct compaction ------------
__global__ __launch_bounds__(T1) void k_fused(const float4* __restrict__ y,
                                              const float4* __restrict__ o,
                                              const float4* __restrict__ w) {
    __shared__ float    stage[STAGE_CAP];
    __shared__ unsigned s_cnt, s_base;
    __shared__ float    rm[8], rp[8];

    const int tid  = threadIdx.x;
    const int warp = tid >> 5;
    const int lane = tid & 31;
    if (tid == 0) s_cnt = 0u;
    __syncthreads();

    const int b     = blockIdx.x / BPB;
    const int chunk = blockIdx.x % BPB;
    const size_t base = (size_t)b * N4 + (size_t)chunk * F4B;
    const float t0 = g_t0[b];

    const ull NEG1 = pk2(-1.0f, -1.0f);
    ull msA = 0ull, msB = 0ull, psA = 0ull, psB = 0ull;   // packed {0,0}

#pragma unroll
    for (int it = 0; it < ITF; ++it) {
        const size_t idx = base + (size_t)it * T1 + tid;
        const float4 yv = y[idx];
        const float4 ov = o[idx];
        const float4 wv = w[idx];

        const ull y01 = pk2(yv.x, yv.y), y23 = pk2(yv.z, yv.w);
        const ull o01 = pk2(ov.x, ov.y), o23 = pk2(ov.z, ov.w);
        const ull w01 = pk2(wv.x, wv.y), w23 = pk2(wv.z, wv.w);

        const ull d01 = fma2(y01, NEG1, o01);      // o - y
        const ull d23 = fma2(y23, NEG1, o23);
        const ull m01 = mul2(d01, d01);
        const ull m23 = mul2(d23, d23);
        msA = add2(msA, m01);  msB = add2(msB, m23);
        psA = fma2(w01, m01, psA);  psB = fma2(w23, m23, psB);

        float m0, m1, m2, m3;
        up2(m01, m0, m1);  up2(m23, m2, m3);

        // cheap OR-chain guard; full predicate only on the rare path
        if (m0 >= t0 || m1 >= t0 || m2 >= t0 || m3 >= t0) {
            if (m0 >= t0 && ov.x > 0.0f && wv.x == 0.0f) stage[atomicAdd(&s_cnt, 1u)] = m0;
            if (m1 >= t0 && ov.y > 0.0f && wv.y == 0.0f) stage[atomicAdd(&s_cnt, 1u)] = m1;
            if (m2 >= t0 && ov.z > 0.0f && wv.z == 0.0f) stage[atomicAdd(&s_cnt, 1u)] = m2;
            if (m3 >= t0 && ov.w > 0.0f && wv.w == 0.0f) stage[atomicAdd(&s_cnt, 1u)] = m3;
        }
    }

    // reduce msum / psum
    float a0, a1, b0, b1, c0, c1, e0, e1;
    up2(msA, a0, a1); up2(msB, b0, b1);
    up2(psA, c0, c1); up2(psB, e0, e1);
    float msum = (a0 + a1) + (b0 + b1);
    float psum = (c0 + c1) + (e0 + e1);
    for (int off = 16; off; off >>= 1) {
        msum += __shfl_down_sync(0xffffffffu, msum, off);
        psum += __shfl_down_sync(0xffffffffu, psum, off);
    }
    if (lane == 0) { rm[warp] = msum; rp[warp] = psum; }
    __syncthreads();                                  // also orders stage writes
    if (tid == 0) {
        double mm = 0.0, pp = 0.0;
#pragma unroll
        for (int i = 0; i < 8; i++) { mm += (double)rm[i]; pp += (double)rp[i]; }
        atomicAdd(&g_msum, mm);
        atomicAdd(&g_psum[b], pp);
    }

    // single end-of-kernel flush of staged survivors
    const unsigned c = s_cnt;
    if (tid == 0 && c) s_base = atomicAdd(&g_cnt2[b], c);
    __syncthreads();
    if (c) {
        float* outp = g_cand2 + (size_t)b * CAP2 + s_base;
        for (unsigned i = tid; i < c; i += T1) outp[i] = stage[i];
    }
}

// ---------------- K4: verify survivor count; arm fallback ------------------
__global__ void k_check() {
    int b = threadIdx.x;
    if (b >= BATCH) return;
    if (g_cnt2[b] < (unsigned)g_k[b]) {      // threshold missed -> take all positives
        g_redo[b] = 1;
        g_cnt2[b] = 0u;
        g_t0[b]   = 1.4e-45f;
    }
}

// ---------------- K5: fallback refilter from inputs (no-op unless armed) ---
__global__ __launch_bounds__(T1) void k_fb(const float4* __restrict__ y,
                                           const float4* __restrict__ o,
                                           const float4* __restrict__ w) {
    const int b = blockIdx.x / BPB;
    if (!g_redo[b]) return;

    __shared__ float    stage[STAGE_CAP];
    __shared__ unsigned s_cnt, s_base;
    const int tid = threadIdx.x;
    if (tid == 0) s_cnt = 0u;
    __syncthreads();

    const int chunk = blockIdx.x % BPB;
    const size_t base = (size_t)b * N4 + (size_t)chunk * F4B;
    const float t0 = g_t0[b];

#pragma unroll
    for (int it = 0; it < ITF; ++it) {
        const size_t idx = base + (size_t)it * T1 + tid;
        const float4 yv = y[idx];
        const float4 ov = o[idx];
        const float4 wv = w[idx];
#define FPROC(c)                                                            \
        {                                                                   \
            float d = ov.c - yv.c;  float m = d * d;                        \
            if (m >= t0 && ov.c > 0.0f && wv.c == 0.0f)                     \
                stage[atomicAdd(&s_cnt, 1u)] = m;                           \
        }
        FPROC(x) FPROC(y) FPROC(z) FPROC(w)
#undef FPROC
    }
    __syncthreads();
    const unsigned c = s_cnt;
    if (tid == 0 && c) s_base = atomicAdd(&g_cnt2[b], c);
    __syncthreads();
    if (c) {
        float* outp = g_cand2 + (size_t)b * CAP2 + s_base;
        for (unsigned i = tid; i < c; i += T1) outp[i] = stage[i];
    }
}

// ---------------- K6: exact top-k sum (1024 thr, 4-way unrolled) -----------
__global__ __launch_bounds__(T2) void k_topk(const float* __restrict__ ts) {
    const int b    = blockIdx.x;
    const int tid  = threadIdx.x;
    const int lane = tid & 31;
    const int warp = tid >> 5;                 // 32 warps

    __shared__ unsigned cnt[256];
    __shared__ unsigned sh_prefix;
    __shared__ int      sh_krem;
    __shared__ double   red[32];

    const float* vals = g_cand2 + (size_t)b * CAP2;
    const unsigned c  = g_cnt2[b];
    const int K = g_k[b];

    double negsum = 0.0;

    if (c <= (unsigned)K) {
        // survivors are ALL positive candidates -> sum all (4-way unrolled)
        float a0 = 0.f, a1 = 0.f, a2 = 0.f, a3 = 0.f;
        unsigned i = tid;
        for (; i + 3u * T2 < c; i += 4u * T2) {
            a0 += vals[i]; a1 += vals[i + T2]; a2 += vals[i + 2u * T2]; a3 += vals[i + 3u * T2];
        }
        for (; i < c; i += T2) a0 += vals[i];
        float acc = (a0 + a1) + (a2 + a3);
        for (int off = 16; off; off >>= 1) acc += __shfl_down_sync(0xffffffffu, acc, off);
        if (lane == 0) red[warp] = (double)acc;
        __syncthreads();
        if (tid == 0) {
#pragma unroll
            for (int i2 = 0; i2 < 32; i2++) negsum += red[i2];
        }
    } else {
        if (tid == 0) { sh_prefix = 0u; sh_krem = K; }
        const unsigned step  = 4u * T2;
        const unsigned cpad4 = ((c + step - 1) / step) * step;  // uniform trips
        for (int r = 0; r < 4; ++r) {
            if (tid < 256) cnt[tid] = 0u;
            __syncthreads();
            const unsigned pfx = sh_prefix;
            const int shift = 24 - 8 * r;
            for (unsigned i0 = tid; i0 < cpad4; i0 += step) {
#pragma unroll
                for (int s = 0; s < 4; ++s) {
                    const unsigned i = i0 + (unsigned)s * T2;
                    const bool valid = (i < c);
                    const unsigned u = valid ? __float_as_uint(vals[i]) : 0u;
                    const bool match = valid && ((r == 0) || ((u >> (32 - 8 * r)) == pfx));
                    const unsigned bin = (u >> shift) & 255u;
                    const unsigned act = __ballot_sync(0xffffffffu, match);
                    if (match) {
                        const unsigned peers = __match_any_sync(act, bin);
                        if (lane == (__ffs(peers) - 1))
                            atomicAdd(&cnt[bin], (unsigned)__popc(peers));
                    }
                }
            }
            __syncthreads();
            if (tid == 0) {
                int krem = sh_krem;
                int chosen = 0;
                for (int bin = 255; bin >= 0; --bin) {
                    if ((unsigned)krem <= cnt[bin]) { chosen = bin; break; }
                    krem -= (int)cnt[bin];
                }
                sh_prefix = (sh_prefix << 8) | (unsigned)chosen;
                sh_krem = krem;
            }
            __syncthreads();
        }
        // sum pass: strictly-above sum (bit compare valid for positive floats)
        const unsigned thr = sh_prefix;
        float a0 = 0.f, a1 = 0.f, a2 = 0.f, a3 = 0.f;
        unsigned i = tid;
        for (; i + 3u * T2 < c; i += 4u * T2) {
            float v0 = vals[i], v1 = vals[i + T2], v2 = vals[i + 2u * T2], v3 = vals[i + 3u * T2];
            if (__float_as_uint(v0) > thr) a0 += v0;
            if (__float_as_uint(v1) > thr) a1 += v1;
            if (__float_as_uint(v2) > thr) a2 += v2;
            if (__float_as_uint(v3) > thr) a3 += v3;
        }
        for (; i < c; i += T2) { float v = vals[i]; if (__float_as_uint(v) > thr) a0 += v; }
        float acc = (a0 + a1) + (a2 + a3);
        for (int off = 16; off; off >>= 1) acc += __shfl_down_sync(0xffffffffu, acc, off);
        if (lane == 0) red[warp] = (double)acc;
        __syncthreads();
        if (tid == 0) {
#pragma unroll
            for (int i2 = 0; i2 < 32; i2++) negsum += red[i2];
            negsum += (double)sh_krem * (double)__uint_as_float(thr);  // ties
        }
    }

    if (tid == 0) {
        const float t = ts[b];
        const double per = (t > 0.f)
            ? (g_psum[b] + negsum) / (double)t     // ALPHA = 1
            : 0.0;
        atomicAdd(&g_train, per);
    }
}

// ---------------- K7: final scalar -----------------------------------------
__global__ void k_final(float* __restrict__ outp) {
    const double train = g_train / (double)BATCH;
    const double mmean = g_msum / ((double)BATCH * (double)NPER);
    outp[0] = (float)((train + mmean) * 10.0);
}

// ---------------- launch ----------------------------------------------------
extern "C" void kernel_launch(void* const* d_in, const int* in_sizes, int n_in,
                              void* d_out, int out_size) {
    const float4* y  = (const float4*)d_in[0];
    const float4* o  = (const float4*)d_in[1];
    const float4* w  = (const float4*)d_in[2];
    const float*  ts = (const float*)d_in[3];

    k_zero  <<<(BATCH * NBINS + T1 - 1) / T1, T1>>>();
    k_hist  <<<BATCH * HBPB, T1>>>(y, o, w);
    k_sel   <<<1, 32>>>(ts);
    k_fused <<<BATCH * BPB, T1>>>(y, o, w);
    k_check <<<1, 32>>>();
    k_fb    <<<BATCH * BPB, T1>>>(y, o, w);
    k_topk  <<<BATCH, T2>>>(ts);
    k_final <<<1, 1>>>((float*)d_out);
}

// round 10
// speedup vs baseline: 2.6516x; 1.2606x over previous
#include <cuda_runtime.h>
#include <cstdint>

typedef unsigned long long ull;

// Problem constants
#define BATCH 16
#define NPER  1310720          // 256*256*20 elements per batch row
#define N4    (NPER/4)         // 327680 float4 per batch
#define T1    256              // threads per block (big passes)
#define T2    1024             // threads per block (top-k)

// fused pass geometry
#define BPB   256              // blocks per batch
#define F4B   (N4/BPB)         // 1280 float4 per block
#define ITF   (F4B/T1)         // 5 iterations per block
#define STAGE_CAP (ITF*T1*4)   // 5120 floats: block can stage ALL its elements

// sample (histogram) pass geometry: 1/8 systematic sample
#define HBPB    80             // blocks per batch
#define HSTRIDE (N4/HBPB)      // 4096 float4 stripe per block
#define HF4     512            // float4 actually read per block (2 iters)
#define SCALE   8              // inverse sample fraction
#define NBINS   1024           // fine bins: float bits >> 21 (exp + 2 mantissa)

#define CAP2  NPER             // per-batch survivor capacity (cannot overflow)

// ---------------- packed f32x2 helpers -------------------------------------
__device__ __forceinline__ ull pk2(float lo, float hi) {
    ull r; asm("mov.b64 %0,{%1,%2};" : "=l"(r) : "f"(lo), "f"(hi)); return r;
}
__device__ __forceinline__ void up2(ull v, float& lo, float& hi) {
    asm("mov.b64 {%0,%1},%2;" : "=f"(lo), "=f"(hi) : "l"(v));
}
__device__ __forceinline__ ull fma2(ull a, ull b, ull c) {
    ull r; asm("fma.rn.f32x2 %0,%1,%2,%3;" : "=l"(r) : "l"(a), "l"(b), "l"(c)); return r;
}
__device__ __forceinline__ ull mul2(ull a, ull b) {
    ull r; asm("mul.rn.f32x2 %0,%1,%2;" : "=l"(r) : "l"(a), "l"(b)); return r;
}
__device__ __forceinline__ ull add2(ull a, ull b) {
    ull r; asm("add.rn.f32x2 %0,%1,%2;" : "=l"(r) : "l"(a), "l"(b)); return r;
}

// ---------------- static device scratch ------------------------------------
__device__ float    g_cand2[(size_t)BATCH * CAP2];   // primary survivors (>= t0)
__device__ float    g_cand3[(size_t)BATCH * CAP2];   // fallback survivors (all positives)
__device__ unsigned g_hist [BATCH * NBINS];          // sampled histogram
__device__ unsigned g_cnt2 [BATCH];
__device__ unsigned g_cnt3 [BATCH];
__device__ double   g_psum [BATCH];
__device__ double   g_msum;
__device__ double   g_train;
__device__ float    g_t0   [BATCH];
__device__ int      g_k    [BATCH];

// ---------------- K0: zero scratch -----------------------------------------
__global__ void k_zero() {
    int i = blockIdx.x * blockDim.x + threadIdx.x;
    if (i < BATCH * NBINS) g_hist[i] = 0u;
    if (i < BATCH) { g_cnt2[i] = 0u; g_cnt3[i] = 0u; g_psum[i] = 0.0; }
    if (i == 0)   { g_msum = 0.0; g_train = 0.0; }
}

// ---------------- K1: sampled histogram (reads 1/8 of inputs) --------------
__global__ __launch_bounds__(T1) void k_hist(const float4* __restrict__ y,
                                             const float4* __restrict__ o,
                                             const float4* __restrict__ w) {
    __shared__ unsigned hist[8][NBINS];          // 32 KB, per-warp privatized
    const int tid  = threadIdx.x;
    const int warp = tid >> 5;

    for (int i = tid; i < 8 * NBINS; i += T1) (&hist[0][0])[i] = 0u;
    __syncthreads();

    const int b = blockIdx.x / HBPB;
    const int j = blockIdx.x % HBPB;
    const size_t base = (size_t)b * N4 + (size_t)j * HSTRIDE;
    unsigned* myh = hist[warp];

#pragma unroll
    for (int it = 0; it < HF4 / T1; ++it) {       // 2 iterations
        const size_t idx = base + (size_t)it * T1 + tid;
        const float4 yv = y[idx];
        const float4 ov = o[idx];
        const float4 wv = w[idx];
#define HPROC(c)                                                            \
        {                                                                   \
            float d = ov.c - yv.c;  float m = d * d;                        \
            if (ov.c > 0.0f && wv.c == 0.0f)                                \
                atomicAdd(&myh[__float_as_uint(m) >> 21], 1u);              \
        }
        HPROC(x) HPROC(y) HPROC(z) HPROC(w)
#undef HPROC
    }
    __syncthreads();
    for (int bin = tid; bin < NBINS; bin += T1) {
        unsigned s = 0;
#pragma unroll
        for (int wp = 0; wp < 8; wp++) s += hist[wp][bin];
        if (s) atomicAdd(&g_hist[b * NBINS + bin], s);
    }
}

// ---------------- K2: parallel threshold selection (suffix-sum scan) -------
__global__ __launch_bounds__(NBINS) void k_sel(const float* __restrict__ ts) {
    __shared__ unsigned s[NBINS];
    const int b   = blockIdx.x;
    const int tid = threadIdx.x;

    long long Kll = (long long)((int)ts[b]) * 3;   // NEG_POS_RATIO
    if (Kll > NPER) Kll = NPER;
    if (Kll < 0)    Kll = 0;
    const unsigned K = (unsigned)Kll;
    if (tid == 0) g_k[b] = (int)K;

    if (K == 0) { if (tid == 0) g_t0[b] = 3.4e38f; return; }

    s[tid] = g_hist[b * NBINS + tid];
    __syncthreads();

    // Hillis-Steele suffix sum: s[i] = sum of bins i..NBINS-1
#pragma unroll
    for (int off = 1; off < NBINS; off <<= 1) {
        unsigned v = (tid + off < NBINS) ? s[tid + off] : 0u;
        __syncthreads();
        s[tid] += v;
        __syncthreads();
    }

    const unsigned target = 2u * K + 64u;          // 2x margin + slack
    // sat(tid) = suffix estimate covers target; monotone non-increasing in tid
    const bool sat = (tid >= 1) && (s[tid] * SCALE >= target);
    const bool next_sat = (tid + 1 < NBINS) && (s[tid + 1] * SCALE >= target);
    if (sat && !next_sat)
        g_t0[b] = __uint_as_float((unsigned)tid << 21);   // boundary: largest sat bin
    if (tid == 1 && !sat)
        g_t0[b] = 1.4e-45f;                               // not enough -> all positives
}

// ---------------- K3: fused main pass: sums + direct compaction ------------
__global__ __launch_bounds__(T1) void k_fused(const float4* __restrict__ y,
                                              const float4* __restrict__ o,
                                              const float4* __restrict__ w) {
    __shared__ float    stage[STAGE_CAP];
    __shared__ unsigned s_cnt, s_base;
    __shared__ float    rm[8], rp[8];

    const int tid  = threadIdx.x;
    const int warp = tid >> 5;
    const int lane = tid & 31;
    if (tid == 0) s_cnt = 0u;
    __syncthreads();

    const int b     = blockIdx.x / BPB;
    const int chunk = blockIdx.x % BPB;
    const size_t base = (size_t)b * N4 + (size_t)chunk * F4B;
    const float t0 = g_t0[b];

    const ull NEG1 = pk2(-1.0f, -1.0f);
    ull msA = 0ull, msB = 0ull, psA = 0ull, psB = 0ull;   // packed {0,0}

#pragma unroll
    for (int it = 0; it < ITF; ++it) {
        const size_t idx = base + (size_t)it * T1 + tid;
        const float4 yv = y[idx];
        const float4 ov = o[idx];
        const float4 wv = w[idx];

        const ull y01 = pk2(yv.x, yv.y), y23 = pk2(yv.z, yv.w);
        const ull o01 = pk2(ov.x, ov.y), o23 = pk2(ov.z, ov.w);
        const ull w01 = pk2(wv.x, wv.y), w23 = pk2(wv.z, wv.w);

        const ull d01 = fma2(y01, NEG1, o01);      // o - y
        const ull d23 = fma2(y23, NEG1, o23);
        const ull m01 = mul2(d01, d01);
        const ull m23 = mul2(d23, d23);
        msA = add2(msA, m01);  msB = add2(msB, m23);
        psA = fma2(w01, m01, psA);  psB = fma2(w23, m23, psB);

        float m0, m1, m2, m3;
        up2(m01, m0, m1);  up2(m23, m2, m3);

        // cheap OR-chain guard; full predicate only on the rare path
        if (m0 >= t0 || m1 >= t0 || m2 >= t0 || m3 >= t0) {
            if (m0 >= t0 && ov.x > 0.0f && wv.x == 0.0f) stage[atomicAdd(&s_cnt, 1u)] = m0;
            if (m1 >= t0 && ov.y > 0.0f && wv.y == 0.0f) stage[atomicAdd(&s_cnt, 1u)] = m1;
            if (m2 >= t0 && ov.z > 0.0f && wv.z == 0.0f) stage[atomicAdd(&s_cnt, 1u)] = m2;
            if (m3 >= t0 && ov.w > 0.0f && wv.w == 0.0f) stage[atomicAdd(&s_cnt, 1u)] = m3;
        }
    }

    // reduce msum / psum
    float a0, a1, b0, b1, c0, c1, e0, e1;
    up2(msA, a0, a1); up2(msB, b0, b1);
    up2(psA, c0, c1); up2(psB, e0, e1);
    float msum = (a0 + a1) + (b0 + b1);
    float psum = (c0 + c1) + (e0 + e1);
    for (int off = 16; off; off >>= 1) {
        msum += __shfl_down_sync(0xffffffffu, msum, off);
        psum += __shfl_down_sync(0xffffffffu, psum, off);
    }
    if (lane == 0) { rm[warp] = msum; rp[warp] = psum; }
    __syncthreads();                                  // also orders stage writes
    if (tid == 0) {
        double mm = 0.0, pp = 0.0;
#pragma unroll
        for (int i = 0; i < 8; i++) { mm += (double)rm[i]; pp += (double)rp[i]; }
        atomicAdd(&g_msum, mm);
        atomicAdd(&g_psum[b], pp);
    }

    // single end-of-kernel flush of staged survivors
    const unsigned c = s_cnt;
    if (tid == 0 && c) s_base = atomicAdd(&g_cnt2[b], c);
    __syncthreads();
    if (c) {
        float* outp = g_cand2 + (size_t)b * CAP2 + s_base;
        for (unsigned i = tid; i < c; i += T1) outp[i] = stage[i];
    }
}

// ---------------- K4: self-deciding fallback (all positives -> g_cand3) ----
__global__ __launch_bounds__(T1) void k_fb(const float4* __restrict__ y,
                                           const float4* __restrict__ o,
                                           const float4* __restrict__ w) {
    const int b = blockIdx.x / BPB;
    if (g_cnt2[b] >= (unsigned)g_k[b]) return;   // primary threshold succeeded

    __shared__ float    stage[STAGE_CAP];
    __shared__ unsigned s_cnt, s_base;
    const int tid = threadIdx.x;
    if (tid == 0) s_cnt = 0u;
    __syncthreads();

    const int chunk = blockIdx.x % BPB;
    const size_t base = (size_t)b * N4 + (size_t)chunk * F4B;

#pragma unroll
    for (int it = 0; it < ITF; ++it) {
        const size_t idx = base + (size_t)it * T1 + tid;
        const float4 yv = y[idx];
        const float4 ov = o[idx];
        const float4 wv = w[idx];
#define FPROC(c)                                                            \
        {                                                                   \
            float d = ov.c - yv.c;  float m = d * d;                        \
            if (m > 0.0f && ov.c > 0.0f && wv.c == 0.0f)                    \
                stage[atomicAdd(&s_cnt, 1u)] = m;                           \
        }
        FPROC(x) FPROC(y) FPROC(z) FPROC(w)
#undef FPROC
    }
    __syncthreads();
    const unsigned c = s_cnt;
    if (tid == 0 && c) s_base = atomicAdd(&g_cnt3[b], c);
    __syncthreads();
    if (c) {
        float* outp = g_cand3 + (size_t)b * CAP2 + s_base;
        for (unsigned i = tid; i < c; i += T1) outp[i] = stage[i];
    }
}

// ---------------- K5: exact top-k sum (1024 thr, 4-way unrolled) -----------
__global__ __launch_bounds__(T2) void k_topk(const float* __restrict__ ts) {
    const int b    = blockIdx.x;
    const int tid  = threadIdx.x;
    const int lane = tid & 31;
    const int warp = tid >> 5;                 // 32 warps

    __shared__ unsigned cnt[256];
    __shared__ unsigned sh_prefix;
    __shared__ int      sh_krem;
    __shared__ double   red[32];

    const int K = g_k[b];
    const unsigned c2 = g_cnt2[b];
    const float* vals;
    unsigned c;
    if (c2 >= (unsigned)K) { vals = g_cand2 + (size_t)b * CAP2; c = c2; }
    else                   { vals = g_cand3 + (size_t)b * CAP2; c = g_cnt3[b]; }

    double negsum = 0.0;

    if (c <= (unsigned)K) {
        // take everything (all positive candidates; zeros contribute 0)
        float a0 = 0.f, a1 = 0.f, a2 = 0.f, a3 = 0.f;
        unsigned i = tid;
        for (; i + 3u * T2 < c; i += 4u * T2) {
            a0 += vals[i]; a1 += vals[i + T2]; a2 += vals[i + 2u * T2]; a3 += vals[i + 3u * T2];
        }
        for (; i < c; i += T2) a0 += vals[i];
        float acc = (a0 + a1) + (a2 + a3);
        for (int off = 16; off; off >>= 1) acc += __shfl_down_sync(0xffffffffu, acc, off);
        if (lane == 0) red[warp] = (double)acc;
        __syncthreads();
        if (tid == 0) {
#pragma unroll
            for (int i2 = 0; i2 < 32; i2++) negsum += red[i2];
        }
    } else {
        if (tid == 0) { sh_prefix = 0u; sh_krem = K; }
        const unsigned step  = 4u * T2;
        const unsigned cpad4 = ((c + step - 1) / step) * step;  // uniform trips
        for (int r = 0; r < 4; ++r) {
            if (tid < 256) cnt[tid] = 0u;
            __syncthreads();
            const unsigned pfx = sh_prefix;
            const int shift = 24 - 8 * r;
            for (unsigned i0 = tid; i0 < cpad4; i0 += step) {
#pragma unroll
                for (int s = 0; s < 4; ++s) {
                    const unsigned i = i0 + (unsigned)s * T2;
                    const bool valid = (i < c);
                    const unsigned u = valid ? __float_as_uint(vals[i]) : 0u;
                    const bool match = valid && ((r == 0) || ((u >> (32 - 8 * r)) == pfx));
                    const unsigned bin = (u >> shift) & 255u;
                    const unsigned act = __ballot_sync(0xffffffffu, match);
                    if (match) {
                        const unsigned peers = __match_any_sync(act, bin);
                        if (lane == (__ffs(peers) - 1))
                            atomicAdd(&cnt[bin], (unsigned)__popc(peers));
                    }
                }
            }
            __syncthreads();
            if (tid == 0) {
                int krem = sh_krem;
                int chosen = 0;
                for (int bin = 255; bin >= 0; --bin) {
                    if ((unsigned)krem <= cnt[bin]) { chosen = bin; break; }
                    krem -= (int)cnt[bin];
                }
                sh_prefix = (sh_prefix << 8) | (unsigned)chosen;
                sh_krem = krem;
            }
            __syncthreads();
        }
        // sum pass: strictly-above sum (bit compare valid for positive floats)
        const unsigned thr = sh_prefix;
        float a0 = 0.f, a1 = 0.f, a2 = 0.f, a3 = 0.f;
        unsigned i = tid;
        for (; i + 3u * T2 < c; i += 4u * T2) {
            float v0 = vals[i], v1 = vals[i + T2], v2 = vals[i + 2u * T2], v3 = vals[i + 3u * T2];
            if (__float_as_uint(v0) > thr) a0 += v0;
            if (__float_as_uint(v1) > thr) a1 += v1;
            if (__float_as_uint(v2) > thr) a2 += v2;
            if (__float_as_uint(v3) > thr) a3 += v3;
        }
        for (; i < c; i += T2) { float v = vals[i]; if (__float_as_uint(v) > thr) a0 += v; }
        float acc = (a0 + a1) + (a2 + a3);
        for (int off = 16; off; off >>= 1) acc += __shfl_down_sync(0xffffffffu, acc, off);
        if (lane == 0) red[warp] = (double)acc;
        __syncthreads();
        if (tid == 0) {
#pragma unroll
            for (int i2 = 0; i2 < 32; i2++) negsum += red[i2];
            negsum += (double)sh_krem * (double)__uint_as_float(thr);  // ties
        }
    }

    if (tid == 0) {
        const float t = ts[b];
        const double per = (t > 0.f)
            ? (g_psum[b] + negsum) / (double)t     // ALPHA = 1
            : 0.0;
        atomicAdd(&g_train, per);
    }
}

// ---------------- K6: final scalar -----------------------------------------
__global__ void k_final(float* __restrict__ outp) {
    const double train = g_train / (double)BATCH;
    const double mmean = g_msum / ((double)BATCH * (double)NPER);
    outp[0] = (float)((train + mmean) * 10.0);
}

// ---------------- launch ----------------------------------------------------
extern "C" void kernel_launch(void* const* d_in, const int* in_sizes, int n_in,
                              void* d_out, int out_size) {
    const float4* y  = (const float4*)d_in[0];
    const float4* o  = (const float4*)d_in[1];
    const float4* w  = (const float4*)d_in[2];
    const float*  ts = (const float*)d_in[3];

    k_zero  <<<(BATCH * NBINS + T1 - 1) / T1, T1>>>();
    k_hist  <<<BATCH * HBPB, T1>>>(y, o, w);
    k_sel   <<<BATCH, NBINS>>>(ts);
    k_fused <<<BATCH * BPB, T1>>>(y, o, w);
    k_fb    <<<BATCH * BPB, T1>>>(y, o, w);
    k_topk  <<<BATCH, T2>>>(ts);
    k_final <<<1, 1>>>((float*)d_out);
}

// round 13
// speedup vs baseline: 2.9062x; 1.0960x over previous
#include <cuda_runtime.h>
#include <cstdint>

typedef unsigned long long ull;

// Problem constants
#define BATCH 16
#define NPER  1310720          // 256*256*20 elements per batch row
#define N4    (NPER/4)         // 327680 float4 per batch
#define T1    256              // threads per block (big passes)
#define T2    1024             // threads per block (top-k)

// fused pass geometry
#define BPB   256              // blocks per batch
#define F4B   (N4/BPB)         // 1280 float4 per block
#define ITF   (F4B/T1)         // 5 iterations per block
#define STAGE_CAP (ITF*T1*4)   // 5120 floats: block can stage ALL its elements

// sample (histogram) pass geometry: 1/16 systematic sample
#define HBPB    80             // blocks per batch
#define HSTRIDE (N4/HBPB)      // 4096 float4 stripe per block
#define HF4     256            // float4 actually read per block (1 iter)
#define SCALE   16             // inverse sample fraction
#define NBINS   1024           // fine bins: float bits >> 21 (exp + 2 mantissa)

#define CAP2  NPER             // per-batch survivor capacity (cannot overflow)

// ---------------- packed f32x2 helpers -------------------------------------
__device__ __forceinline__ ull pk2(float lo, float hi) {
    ull r; asm("mov.b64 %0,{%1,%2};" : "=l"(r) : "f"(lo), "f"(hi)); return r;
}
__device__ __forceinline__ void up2(ull v, float& lo, float& hi) {
    asm("mov.b64 {%0,%1},%2;" : "=f"(lo), "=f"(hi) : "l"(v));
}
__device__ __forceinline__ ull fma2(ull a, ull b, ull c) {
    ull r; asm("fma.rn.f32x2 %0,%1,%2,%3;" : "=l"(r) : "l"(a), "l"(b), "l"(c)); return r;
}
__device__ __forceinline__ ull mul2(ull a, ull b) {
    ull r; asm("mul.rn.f32x2 %0,%1,%2;" : "=l"(r) : "l"(a), "l"(b)); return r;
}
__device__ __forceinline__ ull add2(ull a, ull b) {
    ull r; asm("add.rn.f32x2 %0,%1,%2;" : "=l"(r) : "l"(a), "l"(b)); return r;
}

// ---------------- static device scratch ------------------------------------
__device__ float    g_cand2[(size_t)BATCH * CAP2];   // primary survivors (>= t0)
__device__ float    g_cand3[(size_t)BATCH * CAP2];   // fallback survivors (all positives)
__device__ unsigned g_hist [BATCH * NBINS];          // sampled histogram
__device__ unsigned g_cnt2 [BATCH];
__device__ unsigned g_cnt3 [BATCH];
__device__ double   g_psum [BATCH];
__device__ double   g_msum;
__device__ double   g_train;
__device__ float    g_t0   [BATCH];
__device__ int      g_k    [BATCH];
__device__ unsigned g_done;                          // completion ticket for final fold

// ---------------- K0: zero scratch -----------------------------------------
__global__ void k_zero() {
    int i = blockIdx.x * blockDim.x + threadIdx.x;
    if (i < BATCH * NBINS) g_hist[i] = 0u;
    if (i < BATCH) { g_cnt2[i] = 0u; g_cnt3[i] = 0u; g_psum[i] = 0.0; }
    if (i == 0)   { g_msum = 0.0; g_train = 0.0; g_done = 0u; }
}

// ---------------- K1: sampled histogram (reads 1/16 of inputs) -------------
__global__ __launch_bounds__(T1) void k_hist(const float4* __restrict__ y,
                                             const float4* __restrict__ o,
                                             const float4* __restrict__ w) {
    __shared__ unsigned hist[8][NBINS];          // 32 KB, per-warp privatized
    const int tid  = threadIdx.x;
    const int warp = tid >> 5;

    for (int i = tid; i < 8 * NBINS; i += T1) (&hist[0][0])[i] = 0u;
    __syncthreads();

    const int b = blockIdx.x / HBPB;
    const int j = blockIdx.x % HBPB;
    const size_t base = (size_t)b * N4 + (size_t)j * HSTRIDE;
    unsigned* myh = hist[warp];

#pragma unroll
    for (int it = 0; it < HF4 / T1; ++it) {       // 1 iteration
        const size_t idx = base + (size_t)it * T1 + tid;
        const float4 yv = y[idx];
        const float4 ov = o[idx];
        const float4 wv = w[idx];
#define HPROC(c)                                                            \
        {                                                                   \
            float d = ov.c - yv.c;  float m = d * d;                        \
            if (ov.c > 0.0f && wv.c == 0.0f)                                \
                atomicAdd(&myh[__float_as_uint(m) >> 21], 1u);              \
        }
        HPROC(x) HPROC(y) HPROC(z) HPROC(w)
#undef HPROC
    }
    __syncthreads();
    for (int bin = tid; bin < NBINS; bin += T1) {
        unsigned s = 0;
#pragma unroll
        for (int wp = 0; wp < 8; wp++) s += hist[wp][bin];
        if (s) atomicAdd(&g_hist[b * NBINS + bin], s);
    }
}

// ---------------- K2: parallel threshold selection (suffix-sum scan) -------
__global__ __launch_bounds__(NBINS) void k_sel(const float* __restrict__ ts) {
    __shared__ unsigned s[NBINS];
    const int b   = blockIdx.x;
    const int tid = threadIdx.x;

    long long Kll = (long long)((int)ts[b]) * 3;   // NEG_POS_RATIO
    if (Kll > NPER) Kll = NPER;
    if (Kll < 0)    Kll = 0;
    const unsigned K = (unsigned)Kll;
    if (tid == 0) g_k[b] = (int)K;

    if (K == 0) { if (tid == 0) g_t0[b] = 3.4e38f; return; }

    s[tid] = g_hist[b * NBINS + tid];
    __syncthreads();

    // Hillis-Steele suffix sum: s[i] = sum of bins i..NBINS-1
#pragma unroll
    for (int off = 1; off < NBINS; off <<= 1) {
        unsigned v = (tid + off < NBINS) ? s[tid + off] : 0u;
        __syncthreads();
        s[tid] += v;
        __syncthreads();
    }

    const unsigned target = K + (K >> 2) + 64u;    // 1.25x margin + slack (>=4 sigma)
    // sat(tid) = suffix estimate covers target; monotone non-increasing in tid
    const bool sat = (tid >= 1) && (s[tid] * SCALE >= target);
    const bool next_sat = (tid + 1 < NBINS) && (s[tid + 1] * SCALE >= target);
    if (sat && !next_sat)
        g_t0[b] = __uint_as_float((unsigned)tid << 21);   // boundary: largest sat bin
    if (tid == 1 && !sat)
        g_t0[b] = 1.4e-45f;                               // not enough -> all positives
}

// ---------------- K3: fused main pass: sums + direct compaction ------------
__global__ __launch_bounds__(T1) void k_fused(const float4* __restrict__ y,
                                              const float4* __restrict__ o,
                                              const float4* __restrict__ w) {
    __shared__ float    stage[STAGE_CAP];
    __shared__ unsigned s_cnt, s_base;
    __shared__ float    rm[8], rp[8];

    const int tid  = threadIdx.x;
    const int warp = tid >> 5;
    const int lane = tid & 31;
    if (tid == 0) s_cnt = 0u;
    __syncthreads();

    const int b     = blockIdx.x / BPB;
    const int chunk = blockIdx.x % BPB;
    const size_t base = (size_t)b * N4 + (size_t)chunk * F4B;
    const float t0 = g_t0[b];

    const ull NEG1 = pk2(-1.0f, -1.0f);
    ull msA = 0ull, msB = 0ull, psA = 0ull, psB = 0ull;   // packed {0,0}

#pragma unroll
    for (int it = 0; it < ITF; ++it) {
        const size_t idx = base + (size_t)it * T1 + tid;
        const float4 yv = y[idx];
        const float4 ov = o[idx];
        const float4 wv = w[idx];

        const ull y01 = pk2(yv.x, yv.y), y23 = pk2(yv.z, yv.w);
        const ull o01 = pk2(ov.x, ov.y), o23 = pk2(ov.z, ov.w);
        const ull w01 = pk2(wv.x, wv.y), w23 = pk2(wv.z, wv.w);

        const ull d01 = fma2(y01, NEG1, o01);      // o - y
        const ull d23 = fma2(y23, NEG1, o23);
        const ull m01 = mul2(d01, d01);
        const ull m23 = mul2(d23, d23);
        msA = add2(msA, m01);  msB = add2(msB, m23);
        psA = fma2(w01, m01, psA);  psB = fma2(w23, m23, psB);

        float m0, m1, m2, m3;
        up2(m01, m0, m1);  up2(m23, m2, m3);

        // cheap OR-chain guard; full predicate only on the rare path
        if (m0 >= t0 || m1 >= t0 || m2 >= t0 || m3 >= t0) {
            if (m0 >= t0 && ov.x > 0.0f && wv.x == 0.0f) stage[atomicAdd(&s_cnt, 1u)] = m0;
            if (m1 >= t0 && ov.y > 0.0f && wv.y == 0.0f) stage[atomicAdd(&s_cnt, 1u)] = m1;
            if (m2 >= t0 && ov.z > 0.0f && wv.z == 0.0f) stage[atomicAdd(&s_cnt, 1u)] = m2;
            if (m3 >= t0 && ov.w > 0.0f && wv.w == 0.0f) stage[atomicAdd(&s_cnt, 1u)] = m3;
        }
    }

    // reduce msum / psum
    float a0, a1, b0, b1, c0, c1, e0, e1;
    up2(msA, a0, a1); up2(msB, b0, b1);
    up2(psA, c0, c1); up2(psB, e0, e1);
    float msum = (a0 + a1) + (b0 + b1);
    float psum = (c0 + c1) + (e0 + e1);
    for (int off = 16; off; off >>= 1) {
        msum += __shfl_down_sync(0xffffffffu, msum, off);
        psum += __shfl_down_sync(0xffffffffu, psum, off);
    }
    if (lane == 0) { rm[warp] = msum; rp[warp] = psum; }
    __syncthreads();                                  // also orders stage writes
    if (tid == 0) {
        double mm = 0.0, pp = 0.0;
#pragma unroll
        for (int i = 0; i < 8; i++) { mm += (double)rm[i]; pp += (double)rp[i]; }
        atomicAdd(&g_msum, mm);
        atomicAdd(&g_psum[b], pp);
    }

    // single end-of-kernel flush of staged survivors
    const unsigned c = s_cnt;
    if (tid == 0 && c) s_base = atomicAdd(&g_cnt2[b], c);
    __syncthreads();
    if (c) {
        float* outp = g_cand2 + (size_t)b * CAP2 + s_base;
        for (unsigned i = tid; i < c; i += T1) outp[i] = stage[i];
    }
}

// ---------------- K4: self-deciding fallback (all positives -> g_cand3) ----
__global__ __launch_bounds__(T1) void k_fb(const float4* __restrict__ y,
                                           const float4* __restrict__ o,
                                           const float4* __restrict__ w) {
    const int b = blockIdx.x / BPB;
    if (g_cnt2[b] >= (unsigned)g_k[b]) return;   // primary threshold succeeded

    __shared__ float    stage[STAGE_CAP];
    __shared__ unsigned s_cnt, s_base;
    const int tid = threadIdx.x;
    if (tid == 0) s_cnt = 0u;
    __syncthreads();

    const int chunk = blockIdx.x % BPB;
    const size_t base = (size_t)b * N4 + (size_t)chunk * F4B;

#pragma unroll
    for (int it = 0; it < ITF; ++it) {
        const size_t idx = base + (size_t)it * T1 + tid;
        const float4 yv = y[idx];
        const float4 ov = o[idx];
        const float4 wv = w[idx];
#define FPROC(c)                                                            \
        {                                                                   \
            float d = ov.c - yv.c;  float m = d * d;                        \
            if (m > 0.0f && ov.c > 0.0f && wv.c == 0.0f)                    \
                stage[atomicAdd(&s_cnt, 1u)] = m;                           \
        }
        FPROC(x) FPROC(y) FPROC(z) FPROC(w)
#undef FPROC
    }
    __syncthreads();
    const unsigned c = s_cnt;
    if (tid == 0 && c) s_base = atomicAdd(&g_cnt3[b], c);
    __syncthreads();
    if (c) {
        float* outp = g_cand3 + (size_t)b * CAP2 + s_base;
        for (unsigned i = tid; i < c; i += T1) outp[i] = stage[i];
    }
}

// ---------------- K5: exact top-k sum + merged final fold ------------------
__global__ __launch_bounds__(T2) void k_topk(const float* __restrict__ ts,
                                             float* __restrict__ outp) {
    const int b    = blockIdx.x;
    const int tid  = threadIdx.x;
    const int lane = tid & 31;
    const int warp = tid >> 5;                 // 32 warps

    __shared__ unsigned cnt[256];
    __shared__ unsigned sh_prefix;
    __shared__ int      sh_krem;
    __shared__ double   red[32];

    const int K = g_k[b];
    const unsigned c2 = g_cnt2[b];
    const float* vals;
    unsigned c;
    if (c2 >= (unsigned)K) { vals = g_cand2 + (size_t)b * CAP2; c = c2; }
    else                   { vals = g_cand3 + (size_t)b * CAP2; c = g_cnt3[b]; }

    double negsum = 0.0;

    if (c <= (unsigned)K) {
        // take everything (all positive candidates; zeros contribute 0)
        float a0 = 0.f, a1 = 0.f, a2 = 0.f, a3 = 0.f;
        unsigned i = tid;
        for (; i + 3u * T2 < c; i += 4u * T2) {
            a0 += vals[i]; a1 += vals[i + T2]; a2 += vals[i + 2u * T2]; a3 += vals[i + 3u * T2];
        }
        for (; i < c; i += T2) a0 += vals[i];
        float acc = (a0 + a1) + (a2 + a3);
        for (int off = 16; off; off >>= 1) acc += __shfl_down_sync(0xffffffffu, acc, off);
        if (lane == 0) red[warp] = (double)acc;
        __syncthreads();
        if (tid == 0) {
#pragma unroll
            for (int i2 = 0; i2 < 32; i2++) negsum += red[i2];
        }
    } else {
        if (tid == 0) { sh_prefix = 0u; sh_krem = K; }
        const unsigned step  = 4u * T2;
        const unsigned cpad4 = ((c + step - 1) / step) * step;  // uniform trips
        for (int r = 0; r < 4; ++r) {
            if (tid < 256) cnt[tid] = 0u;
            __syncthreads();
            const unsigned pfx = sh_prefix;
            const int shift = 24 - 8 * r;
            for (unsigned i0 = tid; i0 < cpad4; i0 += step) {
#pragma unroll
                for (int s = 0; s < 4; ++s) {
                    const unsigned i = i0 + (unsigned)s * T2;
                    const bool valid = (i < c);
                    const unsigned u = valid ? __float_as_uint(vals[i]) : 0u;
                    const bool match = valid && ((r == 0) || ((u >> (32 - 8 * r)) == pfx));
                    const unsigned bin = (u >> shift) & 255u;
                    const unsigned act = __ballot_sync(0xffffffffu, match);
                    if (match) {
                        const unsigned peers = __match_any_sync(act, bin);
                        if (lane == (__ffs(peers) - 1))
                            atomicAdd(&cnt[bin], (unsigned)__popc(peers));
                    }
                }
            }
            __syncthreads();
            if (tid == 0) {
                int krem = sh_krem;
                int chosen = 0;
                for (int bin = 255; bin >= 0; --bin) {
                    if ((unsigned)krem <= cnt[bin]) { chosen = bin; break; }
                    krem -= (int)cnt[bin];
                }
                sh_prefix = (sh_prefix << 8) | (unsigned)chosen;
                sh_krem = krem;
            }
            __syncthreads();
        }
        // sum pass: strictly-above sum (bit compare valid for positive floats)
        const unsigned thr = sh_prefix;
        float a0 = 0.f, a1 = 0.f, a2 = 0.f, a3 = 0.f;
        unsigned i = tid;
        for (; i + 3u * T2 < c; i += 4u * T2) {
            float v0 = vals[i], v1 = vals[i + T2], v2 = vals[i + 2u * T2], v3 = vals[i + 3u * T2];
            if (__float_as_uint(v0) > thr) a0 += v0;
            if (__float_as_uint(v1) > thr) a1 += v1;
            if (__float_as_uint(v2) > thr) a2 += v2;
            if (__float_as_uint(v3) > thr) a3 += v3;
        }
        for (; i < c; i += T2) { float v = vals[i]; if (__float_as_uint(v) > thr) a0 += v; }
        float acc = (a0 + a1) + (a2 + a3);
        for (int off = 16; off; off >>= 1) acc += __shfl_down_sync(0xffffffffu, acc, off);
        if (lane == 0) red[warp] = (double)acc;
        __syncthreads();
        if (tid == 0) {
#pragma unroll
            for (int i2 = 0; i2 < 32; i2++) negsum += red[i2];
            negsum += (double)sh_krem * (double)__uint_as_float(thr);  // ties
        }
    }

    if (tid == 0) {
        const float t = ts[b];
        const double per = (t > 0.f)
            ? (g_psum[b] + negsum) / (double)t     // ALPHA = 1
            : 0.0;
        atomicAdd(&g_train, per);
        __threadfence();                            // publish before ticket
        const unsigned ticket = atomicAdd(&g_done, 1u);
        if (ticket == BATCH - 1) {                  // last batch: fold the scalar
            const double train = g_train / (double)BATCH;
            const double mmean = g_msum / ((double)BATCH * (double)NPER);
            outp[0] = (float)((train + mmean) * 10.0);
        }
    }
}

// ---------------- launch ----------------------------------------------------
extern "C" void kernel_launch(void* const* d_in, const int* in_sizes, int n_in,
                              void* d_out, int out_size) {
    const float4* y  = (const float4*)d_in[0];
    const float4* o  = (const float4*)d_in[1];
    const float4* w  = (const float4*)d_in[2];
    const float*  ts = (const float*)d_in[3];

    k_zero  <<<(BATCH * NBINS + T1 - 1) / T1, T1>>>();
    k_hist  <<<BATCH * HBPB, T1>>>(y, o, w);
    k_sel   <<<BATCH, NBINS>>>(ts);
    k_fused <<<BATCH * BPB, T1>>>(y, o, w);
    k_fb    <<<BATCH * BPB, T1>>>(y, o, w);
    k_topk  <<<BATCH, T2>>>(ts, (float*)d_out);
}

// round 14
// speedup vs baseline: 3.2105x; 1.1047x over previous
#include <cuda_runtime.h>
#include <cstdint>

typedef unsigned long long ull;

// Problem constants
#define BATCH 16
#define NPER  1310720          // 256*256*20 elements per batch row
#define N4    (NPER/4)         // 327680 float4 per batch
#define T1    256              // threads per block (big passes)
#define T2    1024             // threads per block (top-k)

// fused pass geometry
#define BPB   256              // blocks per batch
#define F4B   (N4/BPB)         // 1280 float4 per block
#define ITF   (F4B/T1)         // 5 iterations per block
#define STAGE_CAP (ITF*T1*4)   // 5120 floats: block can stage ALL its elements

// sample (histogram) pass geometry: 1/16 systematic sample
#define HBPB    40             // blocks per batch
#define HSTRIDE (N4/HBPB)      // 8192 float4 stripe per block
#define HF4     512            // float4 actually read per block (2 iters)
#define SCALE   16             // inverse sample fraction
#define NBINS   1024           // fine bins: float bits >> 21 (exp + 2 mantissa)
#define HCOPIES 2              // privatized smem histogram copies

#define CAP2  NPER             // per-batch survivor capacity (cannot overflow)

// ---------------- packed f32x2 helpers -------------------------------------
__device__ __forceinline__ ull pk2(float lo, float hi) {
    ull r; asm("mov.b64 %0,{%1,%2};" : "=l"(r) : "f"(lo), "f"(hi)); return r;
}
__device__ __forceinline__ void up2(ull v, float& lo, float& hi) {
    asm("mov.b64 {%0,%1},%2;" : "=f"(lo), "=f"(hi) : "l"(v));
}
__device__ __forceinline__ ull fma2(ull a, ull b, ull c) {
    ull r; asm("fma.rn.f32x2 %0,%1,%2,%3;" : "=l"(r) : "l"(a), "l"(b), "l"(c)); return r;
}
__device__ __forceinline__ ull mul2(ull a, ull b) {
    ull r; asm("mul.rn.f32x2 %0,%1,%2;" : "=l"(r) : "l"(a), "l"(b)); return r;
}
__device__ __forceinline__ ull add2(ull a, ull b) {
    ull r; asm("add.rn.f32x2 %0,%1,%2;" : "=l"(r) : "l"(a), "l"(b)); return r;
}

// ---------------- static device scratch ------------------------------------
// Zero-initialized at module load; every kernel restores its scratch to zero
// after use, so all calls (correctness / capture / replay) see the same state.
__device__ float    g_cand2[(size_t)BATCH * CAP2];   // primary survivors (>= t0)
__device__ float    g_cand3[(size_t)BATCH * CAP2];   // fallback survivors (all positives)
__device__ unsigned g_hist [BATCH * NBINS];          // sampled histogram
__device__ unsigned g_cnt2 [BATCH];
__device__ unsigned g_cnt3 [BATCH];
__device__ double   g_psum [BATCH];
__device__ double   g_msum;
__device__ double   g_train;
__device__ float    g_t0   [BATCH];
__device__ int      g_k    [BATCH];
__device__ unsigned g_done;                          // completion ticket for final fold

// ---------------- K1: sampled histogram (reads 1/16 of inputs) -------------
__global__ __launch_bounds__(T1) void k_hist(const float4* __restrict__ y,
                                             const float4* __restrict__ o,
                                             const float4* __restrict__ w) {
    __shared__ unsigned hist[HCOPIES][NBINS];    // 8 KB, 2 privatized copies
    const int tid  = threadIdx.x;
    const int copy = (tid >> 5) & (HCOPIES - 1);

    for (int i = tid; i < HCOPIES * NBINS; i += T1) (&hist[0][0])[i] = 0u;
    __syncthreads();

    const int b = blockIdx.x / HBPB;
    const int j = blockIdx.x % HBPB;
    const size_t base = (size_t)b * N4 + (size_t)j * HSTRIDE;
    unsigned* myh = hist[copy];

#pragma unroll
    for (int it = 0; it < HF4 / T1; ++it) {       // 2 iterations
        const size_t idx = base + (size_t)it * T1 + tid;
        const float4 yv = y[idx];
        const float4 ov = o[idx];
        const float4 wv = w[idx];
#define HPROC(c)                                                            \
        {                                                                   \
            float d = ov.c - yv.c;  float m = d * d;                        \
            if (ov.c > 0.0f && wv.c == 0.0f)                                \
                atomicAdd(&myh[__float_as_uint(m) >> 21], 1u);              \
        }
        HPROC(x) HPROC(y) HPROC(z) HPROC(w)
#undef HPROC
    }
    __syncthreads();
    for (int bin = tid; bin < NBINS; bin += T1) {
        unsigned s = 0;
#pragma unroll
        for (int cp = 0; cp < HCOPIES; cp++) s += hist[cp][bin];
        if (s) atomicAdd(&g_hist[b * NBINS + bin], s);
    }
}

// ---------------- K2: parallel threshold selection (suffix-sum scan) -------
// Also re-zeroes g_hist for the next invocation.
__global__ __launch_bounds__(NBINS) void k_sel(const float* __restrict__ ts) {
    __shared__ unsigned s[NBINS];
    const int b   = blockIdx.x;
    const int tid = threadIdx.x;

    long long Kll = (long long)((int)ts[b]) * 3;   // NEG_POS_RATIO
    if (Kll > NPER) Kll = NPER;
    if (Kll < 0)    Kll = 0;
    const unsigned K = (unsigned)Kll;
    if (tid == 0) g_k[b] = (int)K;

    // load histogram and reset it for the next run (unconditionally)
    s[tid] = g_hist[b * NBINS + tid];
    g_hist[b * NBINS + tid] = 0u;
    __syncthreads();

    if (K == 0) { if (tid == 0) g_t0[b] = 3.4e38f; return; }

    // Hillis-Steele suffix sum: s[i] = sum of bins i..NBINS-1
#pragma unroll
    for (int off = 1; off < NBINS; off <<= 1) {
        unsigned v = (tid + off < NBINS) ? s[tid + off] : 0u;
        __syncthreads();
        s[tid] += v;
        __syncthreads();
    }

    const unsigned target = K + (K >> 2) + 64u;    // 1.25x margin + slack
    const bool sat = (tid >= 1) && (s[tid] * SCALE >= target);
    const bool next_sat = (tid + 1 < NBINS) && (s[tid + 1] * SCALE >= target);
    if (sat && !next_sat)
        g_t0[b] = __uint_as_float((unsigned)tid << 21);   // largest sat bin
    if (tid == 1 && !sat)
        g_t0[b] = 1.4e-45f;                               // not enough -> all positives
}

// ---------------- K3: fused main pass: sums + direct compaction ------------
__global__ __launch_bounds__(T1) void k_fused(const float4* __restrict__ y,
                                              const float4* __restrict__ o,
                                              const float4* __restrict__ w) {
    __shared__ float    stage[STAGE_CAP];
    __shared__ unsigned s_cnt, s_base;
    __shared__ float    rm[8], rp[8];

    const int tid  = threadIdx.x;
    const int warp = tid >> 5;
    const int lane = tid & 31;
    if (tid == 0) s_cnt = 0u;
    __syncthreads();

    const int b     = blockIdx.x / BPB;
    const int chunk = blockIdx.x % BPB;
    const size_t base = (size_t)b * N4 + (size_t)chunk * F4B;
    const float t0 = g_t0[b];

    const ull NEG1 = pk2(-1.0f, -1.0f);
    ull msA = 0ull, msB = 0ull, psA = 0ull, psB = 0ull;   // packed {0,0}

#pragma unroll
    for (int it = 0; it < ITF; ++it) {
        const size_t idx = base + (size_t)it * T1 + tid;
        const float4 yv = y[idx];
        const float4 ov = o[idx];
        const float4 wv = w[idx];

        const ull y01 = pk2(yv.x, yv.y), y23 = pk2(yv.z, yv.w);
        const ull o01 = pk2(ov.x, ov.y), o23 = pk2(ov.z, ov.w);
        const ull w01 = pk2(wv.x, wv.y), w23 = pk2(wv.z, wv.w);

        const ull d01 = fma2(y01, NEG1, o01);      // o - y
        const ull d23 = fma2(y23, NEG1, o23);
        const ull m01 = mul2(d01, d01);
        const ull m23 = mul2(d23, d23);
        msA = add2(msA, m01);  msB = add2(msB, m23);
        psA = fma2(w01, m01, psA);  psB = fma2(w23, m23, psB);

        float m0, m1, m2, m3;
        up2(m01, m0, m1);  up2(m23, m2, m3);

        // cheap OR-chain guard; full predicate only on the rare path
        if (m0 >= t0 || m1 >= t0 || m2 >= t0 || m3 >= t0) {
            if (m0 >= t0 && ov.x > 0.0f && wv.x == 0.0f) stage[atomicAdd(&s_cnt, 1u)] = m0;
            if (m1 >= t0 && ov.y > 0.0f && wv.y == 0.0f) stage[atomicAdd(&s_cnt, 1u)] = m1;
            if (m2 >= t0 && ov.z > 0.0f && wv.z == 0.0f) stage[atomicAdd(&s_cnt, 1u)] = m2;
            if (m3 >= t0 && ov.w > 0.0f && wv.w == 0.0f) stage[atomicAdd(&s_cnt, 1u)] = m3;
        }
    }

    // reduce msum / psum
    float a0, a1, b0, b1, c0, c1, e0, e1;
    up2(msA, a0, a1); up2(msB, b0, b1);
    up2(psA, c0, c1); up2(psB, e0, e1);
    float msum = (a0 + a1) + (b0 + b1);
    float psum = (c0 + c1) + (e0 + e1);
    for (int off = 16; off; off >>= 1) {
        msum += __shfl_down_sync(0xffffffffu, msum, off);
        psum += __shfl_down_sync(0xffffffffu, psum, off);
    }
    if (lane == 0) { rm[warp] = msum; rp[warp] = psum; }
    __syncthreads();                                  // also orders stage writes
    if (tid == 0) {
        double mm = 0.0, pp = 0.0;
#pragma unroll
        for (int i = 0; i < 8; i++) { mm += (double)rm[i]; pp += (double)rp[i]; }
        atomicAdd(&g_msum, mm);
        atomicAdd(&g_psum[b], pp);
    }

    // single end-of-kernel flush of staged survivors
    const unsigned c = s_cnt;
    if (tid == 0 && c) s_base = atomicAdd(&g_cnt2[b], c);
    __syncthreads();
    if (c) {
        float* outp = g_cand2 + (size_t)b * CAP2 + s_base;
        for (unsigned i = tid; i < c; i += T1) outp[i] = stage[i];
    }
}

// ---------------- K4: self-deciding fallback (all positives -> g_cand3) ----
__global__ __launch_bounds__(T1) void k_fb(const float4* __restrict__ y,
                                           const float4* __restrict__ o,
                                           const float4* __restrict__ w) {
    const int b = blockIdx.x / BPB;
    if (g_cnt2[b] >= (unsigned)g_k[b]) return;   // primary threshold succeeded

    __shared__ float    stage[STAGE_CAP];
    __shared__ unsigned s_cnt, s_base;
    const int tid = threadIdx.x;
    if (tid == 0) s_cnt = 0u;
    __syncthreads();

    const int chunk = blockIdx.x % BPB;
    const size_t base = (size_t)b * N4 + (size_t)chunk * F4B;

#pragma unroll
    for (int it = 0; it < ITF; ++it) {
        const size_t idx = base + (size_t)it * T1 + tid;
        const float4 yv = y[idx];
        const float4 ov = o[idx];
        const float4 wv = w[idx];
#define FPROC(c)                                                            \
        {                                                                   \
            float d = ov.c - yv.c;  float m = d * d;                        \
            if (m > 0.0f && ov.c > 0.0f && wv.c == 0.0f)                    \
                stage[atomicAdd(&s_cnt, 1u)] = m;                           \
        }
        FPROC(x) FPROC(y) FPROC(z) FPROC(w)
#undef FPROC
    }
    __syncthreads();
    const unsigned c = s_cnt;
    if (tid == 0 && c) s_base = atomicAdd(&g_cnt3[b], c);
    __syncthreads();
    if (c) {
        float* outp = g_cand3 + (size_t)b * CAP2 + s_base;
        for (unsigned i = tid; i < c; i += T1) outp[i] = stage[i];
    }
}

// ---------------- K5: exact top-k sum + final fold + scratch reset ---------
__global__ __launch_bounds__(T2) void k_topk(const float* __restrict__ ts,
                                             float* __restrict__ outp) {
    const int b    = blockIdx.x;
    const int tid  = threadIdx.x;
    const int lane = tid & 31;
    const int warp = tid >> 5;                 // 32 warps

    __shared__ unsigned cnt[256];
    __shared__ unsigned sfx[256];
    __shared__ unsigned sh_prefix;
    __shared__ int      sh_krem;
    __shared__ double   red[32];

    const int K = g_k[b];
    const unsigned c2 = g_cnt2[b];
    const float* vals;
    unsigned c;
    if (c2 >= (unsigned)K) { vals = g_cand2 + (size_t)b * CAP2; c = c2; }
    else                   { vals = g_cand3 + (size_t)b * CAP2; c = g_cnt3[b]; }

    double negsum = 0.0;

    if (c <= (unsigned)K) {
        // take everything (all positive candidates; zeros contribute 0)
        float a0 = 0.f, a1 = 0.f, a2 = 0.f, a3 = 0.f;
        unsigned i = tid;
        for (; i + 3u * T2 < c; i += 4u * T2) {
            a0 += vals[i]; a1 += vals[i + T2]; a2 += vals[i + 2u * T2]; a3 += vals[i + 3u * T2];
        }
        for (; i < c; i += T2) a0 += vals[i];
        float acc = (a0 + a1) + (a2 + a3);
        for (int off = 16; off; off >>= 1) acc += __shfl_down_sync(0xffffffffu, acc, off);
        if (lane == 0) red[warp] = (double)acc;
        __syncthreads();
        if (tid == 0) {
#pragma unroll
            for (int i2 = 0; i2 < 32; i2++) negsum += red[i2];
        }
    } else {
        if (tid == 0) { sh_prefix = 0u; sh_krem = K; }
        const unsigned step  = 4u * T2;
        const unsigned cpad4 = ((c + step - 1) / step) * step;  // uniform trips
        for (int r = 0; r < 4; ++r) {
            if (tid < 256) cnt[tid] = 0u;
            __syncthreads();
            const unsigned pfx = sh_prefix;
            const int shift = 24 - 8 * r;
            for (unsigned i0 = tid; i0 < cpad4; i0 += step) {
#pragma unroll
                for (int s = 0; s < 4; ++s) {
                    const unsigned i = i0 + (unsigned)s * T2;
                    const bool valid = (i < c);
                    const unsigned u = valid ? __float_as_uint(vals[i]) : 0u;
                    const bool match = valid && ((r == 0) || ((u >> (32 - 8 * r)) == pfx));
                    const unsigned bin = (u >> shift) & 255u;
                    const unsigned act = __ballot_sync(0xffffffffu, match);
                    if (match) {
                        const unsigned peers = __match_any_sync(act, bin);
                        if (lane == (__ffs(peers) - 1))
                            atomicAdd(&cnt[bin], (unsigned)__popc(peers));
                    }
                }
            }
            __syncthreads();

            // parallel bin selection: suffix-sum over 256 bins (8 steps)
            if (tid < 256) sfx[tid] = cnt[tid];
            __syncthreads();
#pragma unroll
            for (int off = 1; off < 256; off <<= 1) {
                unsigned v = 0;
                if (tid < 256 && tid + off < 256) v = sfx[tid + off];
                __syncthreads();
                if (tid < 256) sfx[tid] += v;
                __syncthreads();
            }
            const unsigned krem_l = (unsigned)sh_krem;     // snapshot before update
            __syncthreads();
            if (tid < 256) {
                // invariant: sfx[0] >= krem_l, so a boundary exists
                const bool sat  = sfx[tid] >= krem_l;
                const bool nsat = (tid + 1 < 256) && (sfx[tid + 1] >= krem_l);
                if (sat && !nsat) {
                    sh_prefix = (sh_prefix << 8) | (unsigned)tid;
                    sh_krem   = (int)(krem_l - ((tid + 1 < 256) ? sfx[tid + 1] : 0u));
                }
            }
            __syncthreads();
        }
        // sum pass: strictly-above sum (bit compare valid for positive floats)
        const unsigned thr = sh_prefix;
        float a0 = 0.f, a1 = 0.f, a2 = 0.f, a3 = 0.f;
        unsigned i = tid;
        for (; i + 3u * T2 < c; i += 4u * T2) {
            float v0 = vals[i], v1 = vals[i + T2], v2 = vals[i + 2u * T2], v3 = vals[i + 3u * T2];
            if (__float_as_uint(v0) > thr) a0 += v0;
            if (__float_as_uint(v1) > thr) a1 += v1;
            if (__float_as_uint(v2) > thr) a2 += v2;
            if (__float_as_uint(v3) > thr) a3 += v3;
        }
        for (; i < c; i += T2) { float v = vals[i]; if (__float_as_uint(v) > thr) a0 += v; }
        float acc = (a0 + a1) + (a2 + a3);
        for (int off = 16; off; off >>= 1) acc += __shfl_down_sync(0xffffffffu, acc, off);
        if (lane == 0) red[warp] = (double)acc;
        __syncthreads();
        if (tid == 0) {
#pragma unroll
            for (int i2 = 0; i2 < 32; i2++) negsum += red[i2];
            negsum += (double)sh_krem * (double)__uint_as_float(thr);  // ties
        }
    }

    if (tid == 0) {
        const float t = ts[b];
        const double per = (t > 0.f)
            ? (g_psum[b] + negsum) / (double)t     // ALPHA = 1
            : 0.0;
        atomicAdd(&g_train, per);

        // reset per-batch scratch for next invocation (after all reads)
        g_cnt2[b] = 0u;
        g_cnt3[b] = 0u;
        g_psum[b] = 0.0;

        __threadfence();                            // publish before ticket
        const unsigned ticket = atomicAdd(&g_done, 1u);
        if (ticket == BATCH - 1) {                  // last batch: fold the scalar
            const double train = g_train / (double)BATCH;
            const double mmean = g_msum / ((double)BATCH * (double)NPER);
            outp[0] = (float)((train + mmean) * 10.0);
            // reset global scratch for next invocation
            g_msum  = 0.0;
            g_train = 0.0;
            g_done  = 0u;
        }
    }
}

// ---------------- launch ----------------------------------------------------
extern "C" void kernel_launch(void* const* d_in, const int* in_sizes, int n_in,
                              void* d_out, int out_size) {
    const float4* y  = (const float4*)d_in[0];
    const float4* o  = (const float4*)d_in[1];
    const float4* w  = (const float4*)d_in[2];
    const float*  ts = (const float*)d_in[3];

    k_hist  <<<BATCH * HBPB, T1>>>(y, o, w);
    k_sel   <<<BATCH, NBINS>>>(ts);
    k_fused <<<BATCH * BPB, T1>>>(y, o, w);
    k_fb    <<<BATCH * BPB, T1>>>(y, o, w);
    k_topk  <<<BATCH, T2>>>(ts, (float*)d_out);
}

// round 17
// speedup vs baseline: 3.2688x; 1.0181x over previous
#include <cuda_runtime.h>
#include <cstdint>

typedef unsigned long long ull;

// Problem constants
#define BATCH 16
#define NPER  1310720          // 256*256*20 elements per batch row
#define N4    (NPER/4)         // 327680 float4 per batch
#define T1    256              // threads per block (big passes)
#define T2    1024             // threads per block (top-k)

// fused pass geometry
#define BPB   256              // blocks per batch
#define F4B   (N4/BPB)         // 1280 float4 per block
#define ITF   (F4B/T1)         // 5 iterations per block
#define STAGE_CAP (ITF*T1*4)   // 5120 floats: block can stage ALL its elements

// sample (histogram) pass geometry: 1/16 systematic sample
#define HBPB    40             // blocks per batch
#define HSTRIDE (N4/HBPB)      // 8192 float4 stripe per block
#define HF4     512            // float4 actually read per block (2 iters)
#define SCALE   16             // inverse sample fraction
#define NBINS   1024           // fine bins: float bits >> 21 (exp + 2 mantissa)
#define HCOPIES 2              // privatized smem histogram copies

#define CAP2  NPER             // per-batch survivor capacity (cannot overflow)

// ---------------- packed f32x2 helpers -------------------------------------
__device__ __forceinline__ ull pk2(float lo, float hi) {
    ull r; asm("mov.b64 %0,{%1,%2};" : "=l"(r) : "f"(lo), "f"(hi)); return r;
}
__device__ __forceinline__ void up2(ull v, float& lo, float& hi) {
    asm("mov.b64 {%0,%1},%2;" : "=f"(lo), "=f"(hi) : "l"(v));
}
__device__ __forceinline__ ull fma2(ull a, ull b, ull c) {
    ull r; asm("fma.rn.f32x2 %0,%1,%2,%3;" : "=l"(r) : "l"(a), "l"(b), "l"(c)); return r;
}
__device__ __forceinline__ ull mul2(ull a, ull b) {
    ull r; asm("mul.rn.f32x2 %0,%1,%2;" : "=l"(r) : "l"(a), "l"(b)); return r;
}
__device__ __forceinline__ ull add2(ull a, ull b) {
    ull r; asm("add.rn.f32x2 %0,%1,%2;" : "=l"(r) : "l"(a), "l"(b)); return r;
}

// ---------------- static device scratch ------------------------------------
// Zero-initialized at module load; every kernel restores its scratch to zero
// after use, so all calls (correctness / capture / replay) see the same state.
__device__ float    g_cand2[(size_t)BATCH * CAP2];   // primary survivors (>= t0)
__device__ float    g_cand3[(size_t)BATCH * CAP2];   // fallback survivors (all positives)
__device__ unsigned g_hist [BATCH * NBINS];          // sampled histogram
__device__ unsigned g_hdone[BATCH];                  // per-batch hist completion ticket
__device__ unsigned g_cnt2 [BATCH];
__device__ unsigned g_cnt3 [BATCH];
__device__ double   g_psum [BATCH];
__device__ double   g_msum;
__device__ double   g_train;
__device__ float    g_t0   [BATCH];
__device__ int      g_k    [BATCH];
__device__ unsigned g_done;                          // completion ticket for final fold

// ---------------- K1: sampled histogram + fused threshold selection --------
__global__ __launch_bounds__(T1) void k_hist(const float4* __restrict__ y,
                                             const float4* __restrict__ o,
                                             const float4* __restrict__ w,
                                             const float*  __restrict__ ts) {
    __shared__ unsigned hist[HCOPIES][NBINS];    // 8 KB, 2 privatized copies
    const int tid  = threadIdx.x;
    const int copy = (tid >> 5) & (HCOPIES - 1);

    for (int i = tid; i < HCOPIES * NBINS; i += T1) (&hist[0][0])[i] = 0u;
    __syncthreads();

    const int b = blockIdx.x / HBPB;
    const int j = blockIdx.x % HBPB;
    const size_t base = (size_t)b * N4 + (size_t)j * HSTRIDE;
    unsigned* myh = hist[copy];

#pragma unroll
    for (int it = 0; it < HF4 / T1; ++it) {       // 2 iterations
        const size_t idx = base + (size_t)it * T1 + tid;
        const float4 yv = y[idx];
        const float4 ov = o[idx];
        const float4 wv = w[idx];
#define HPROC(c)                                                            \
        {                                                                   \
            float d = ov.c - yv.c;  float m = d * d;                        \
            if (ov.c > 0.0f && wv.c == 0.0f)                                \
                atomicAdd(&myh[__float_as_uint(m) >> 21], 1u);              \
        }
        HPROC(x) HPROC(y) HPROC(z) HPROC(w)
#undef HPROC
    }
    __syncthreads();
    for (int bin = tid; bin < NBINS; bin += T1) {
        unsigned s = 0;
#pragma unroll
        for (int cp = 0; cp < HCOPIES; cp++) s += hist[cp][bin];
        if (s) atomicAdd(&g_hist[b * NBINS + bin], s);
    }

    // ---- last-arriving block for this batch performs the selection ----
    __threadfence();                             // publish hist adds before ticket
    __shared__ unsigned s_ticket;
    if (tid == 0) s_ticket = atomicAdd(&g_hdone[b], 1u);
    __syncthreads();
    if (s_ticket != HBPB - 1) return;

    __shared__ unsigned p[256];
    __shared__ int      s_maxbin;
    __shared__ unsigned s_K;
    if (tid == 0) {
        long long Kll = (long long)((int)ts[b]) * 3;   // NEG_POS_RATIO
        if (Kll > NPER) Kll = NPER;
        if (Kll < 0)    Kll = 0;
        g_k[b]   = (int)Kll;
        s_K      = (unsigned)Kll;
        s_maxbin = -1;
        g_hdone[b] = 0u;                         // reset ticket for next call
    }
    __syncthreads();

    // each thread owns 4 bins: load (L2, past our own atomics) and zero them
    unsigned v0, v1, v2, v3;
    {
        unsigned* hp = &g_hist[b * NBINS + 4 * tid];
        v0 = __ldcg(&hp[0]); v1 = __ldcg(&hp[1]);
        v2 = __ldcg(&hp[2]); v3 = __ldcg(&hp[3]);
        hp[0] = 0u; hp[1] = 0u; hp[2] = 0u; hp[3] = 0u;
    }
    p[tid] = v0 + v1 + v2 + v3;
    __syncthreads();

    // suffix-sum over the 256 group sums (Hillis-Steele)
#pragma unroll
    for (int off = 1; off < 256; off <<= 1) {
        unsigned t = (tid + off < 256) ? p[tid + off] : 0u;
        __syncthreads();
        p[tid] += t;
        __syncthreads();
    }

    if (s_K == 0) {
        if (tid == 0) g_t0[b] = 3.4e38f;
        return;
    }
    const unsigned target = s_K + (s_K >> 2) + 64u;     // 1.25x margin + slack
    const unsigned Pnext = (tid + 1 < 256) ? p[tid + 1] : 0u;
    // bin-level suffix S(4t+i) = Pnext + sum_{j>=i} v_j ; find max sat bin >= 1
    int local = -1;
    unsigned suf = Pnext;
    suf += v3; if (4 * tid + 3 >= 1 && suf * SCALE >= target) local = 4 * tid + 3;
    if (local < 0) { suf += v2; if (4 * tid + 2 >= 1 && suf * SCALE >= target) local = 4 * tid + 2; }
    else suf += v2;
    if (local < 0) { suf += v1; if (4 * tid + 1 >= 1 && suf * SCALE >= target) local = 4 * tid + 1; }
    else suf += v1;
    if (local < 0) { suf += v0; if (4 * tid     >= 1 && suf * SCALE >= target) local = 4 * tid;     }
    if (local >= 0) atomicMax(&s_maxbin, local);
    __syncthreads();
    if (tid == 0)
        g_t0[b] = (s_maxbin < 0) ? 1.4e-45f
                                 : __uint_as_float((unsigned)s_maxbin << 21);
}

// ---------------- K3: fused main pass: sums + direct compaction ------------
__global__ __launch_bounds__(T1) void k_fused(const float4* __restrict__ y,
                                              const float4* __restrict__ o,
                                              const float4* __restrict__ w) {
    __shared__ float    stage[STAGE_CAP];
    __shared__ unsigned s_cnt, s_base;
    __shared__ float    rm[8], rp[8];

    const int tid  = threadIdx.x;
    const int warp = tid >> 5;
    const int lane = tid & 31;
    if (tid == 0) s_cnt = 0u;
    __syncthreads();

    const int b     = blockIdx.x / BPB;
    const int chunk = blockIdx.x % BPB;
    const size_t base = (size_t)b * N4 + (size_t)chunk * F4B;
    const float t0 = g_t0[b];

    const ull NEG1 = pk2(-1.0f, -1.0f);
    ull msA = 0ull, msB = 0ull, psA = 0ull, psB = 0ull;   // packed {0,0}

#pragma unroll
    for (int it = 0; it < ITF; ++it) {
        const size_t idx = base + (size_t)it * T1 + tid;
        const float4 yv = y[idx];
        const float4 ov = o[idx];
        const float4 wv = w[idx];

        const ull y01 = pk2(yv.x, yv.y), y23 = pk2(yv.z, yv.w);
        const ull o01 = pk2(ov.x, ov.y), o23 = pk2(ov.z, ov.w);
        const ull w01 = pk2(wv.x, wv.y), w23 = pk2(wv.z, wv.w);

        const ull d01 = fma2(y01, NEG1, o01);      // o - y
        const ull d23 = fma2(y23, NEG1, o23);
        const ull m01 = mul2(d01, d01);
        const ull m23 = mul2(d23, d23);
        msA = add2(msA, m01);  msB = add2(msB, m23);
        psA = fma2(w01, m01, psA);  psB = fma2(w23, m23, psB);

        float m0, m1, m2, m3;
        up2(m01, m0, m1);  up2(m23, m2, m3);

        // cheap OR-chain guard; full predicate only on the rare path
        if (m0 >= t0 || m1 >= t0 || m2 >= t0 || m3 >= t0) {
            if (m0 >= t0 && ov.x > 0.0f && wv.x == 0.0f) stage[atomicAdd(&s_cnt, 1u)] = m0;
            if (m1 >= t0 && ov.y > 0.0f && wv.y == 0.0f) stage[atomicAdd(&s_cnt, 1u)] = m1;
            if (m2 >= t0 && ov.z > 0.0f && wv.z == 0.0f) stage[atomicAdd(&s_cnt, 1u)] = m2;
            if (m3 >= t0 && ov.w > 0.0f && wv.w == 0.0f) stage[atomicAdd(&s_cnt, 1u)] = m3;
        }
    }

    // reduce msum / psum
    float a0, a1, b0, b1, c0, c1, e0, e1;
    up2(msA, a0, a1); up2(msB, b0, b1);
    up2(psA, c0, c1); up2(psB, e0, e1);
    float msum = (a0 + a1) + (b0 + b1);
    float psum = (c0 + c1) + (e0 + e1);
    for (int off = 16; off; off >>= 1) {
        msum += __shfl_down_sync(0xffffffffu, msum, off);
        psum += __shfl_down_sync(0xffffffffu, psum, off);
    }
    if (lane == 0) { rm[warp] = msum; rp[warp] = psum; }
    __syncthreads();                                  // also orders stage writes
    if (tid == 0) {
        double mm = 0.0, pp = 0.0;
#pragma unroll
        for (int i = 0; i < 8; i++) { mm += (double)rm[i]; pp += (double)rp[i]; }
        atomicAdd(&g_msum, mm);
        atomicAdd(&g_psum[b], pp);
    }

    // single end-of-kernel flush of staged survivors
    const unsigned c = s_cnt;
    if (tid == 0 && c) s_base = atomicAdd(&g_cnt2[b], c);
    __syncthreads();
    if (c) {
        float* outp = g_cand2 + (size_t)b * CAP2 + s_base;
        for (unsigned i = tid; i < c; i += T1) outp[i] = stage[i];
    }
}

// ---------------- K4: stage-less fallback (all positives -> g_cand3) -------
__global__ __launch_bounds__(T1) void k_fb(const float4* __restrict__ y,
                                           const float4* __restrict__ o,
                                           const float4* __restrict__ w) {
    const int b = blockIdx.x / BPB;
    if (g_cnt2[b] >= (unsigned)g_k[b]) return;   // primary threshold succeeded

    const int tid  = threadIdx.x;
    const int lane = tid & 31;
    const unsigned lt = (1u << lane) - 1u;
    const int chunk = blockIdx.x % BPB;
    const size_t base = (size_t)b * N4 + (size_t)chunk * F4B;
    float* outp = g_cand3 + (size_t)b * CAP2;

#pragma unroll
    for (int it = 0; it < ITF; ++it) {           // uniform trips: collectives safe
        const size_t idx = base + (size_t)it * T1 + tid;
        const float4 yv = y[idx];
        const float4 ov = o[idx];
        const float4 wv = w[idx];
        float d0 = ov.x - yv.x, d1 = ov.y - yv.y, d2 = ov.z - yv.z, d3 = ov.w - yv.w;
        float q0 = d0 * d0, q1 = d1 * d1, q2 = d2 * d2, q3 = d3 * d3;
        const bool p0 = q0 > 0.0f && ov.x > 0.0f && wv.x == 0.0f;
        const bool p1 = q1 > 0.0f && ov.y > 0.0f && wv.y == 0.0f;
        const bool p2 = q2 > 0.0f && ov.z > 0.0f && wv.z == 0.0f;
        const bool p3 = q3 > 0.0f && ov.w > 0.0f && wv.w == 0.0f;
        const unsigned b0m = __ballot_sync(0xffffffffu, p0);
        const unsigned b1m = __ballot_sync(0xffffffffu, p1);
        const unsigned b2m = __ballot_sync(0xffffffffu, p2);
        const unsigned b3m = __ballot_sync(0xffffffffu, p3);
        const unsigned n0 = __popc(b0m), n1 = __popc(b1m), n2 = __popc(b2m);
        const unsigned tot = n0 + n1 + n2 + __popc(b3m);
        if (tot == 0) continue;                  // warp-uniform
        unsigned basew = 0;
        if (lane == 0) basew = atomicAdd(&g_cnt3[b], tot);
        basew = __shfl_sync(0xffffffffu, basew, 0);
        if (p0) outp[basew + __popc(b0m & lt)] = q0;
        if (p1) outp[basew + n0 + __popc(b1m & lt)] = q1;
        if (p2) outp[basew + n0 + n1 + __popc(b2m & lt)] = q2;
        if (p3) outp[basew + n0 + n1 + n2 + __popc(b3m & lt)] = q3;
    }
}

// ---------------- K5: exact top-k sum + final fold + scratch reset ---------
__global__ __launch_bounds__(T2) void k_topk(const float* __restrict__ ts,
                                             float* __restrict__ outp) {
    const int b    = blockIdx.x;
    const int tid  = threadIdx.x;
    const int lane = tid & 31;
    const int warp = tid >> 5;                 // 32 warps

    __shared__ unsigned cnt[256];
    __shared__ unsigned sfx[256];
    __shared__ unsigned sh_prefix;
    __shared__ int      sh_krem;
    __shared__ double   red[32];

    const int K = g_k[b];
    const unsigned c2 = g_cnt2[b];
    const float* vals;
    unsigned c;
    if (c2 >= (unsigned)K) { vals = g_cand2 + (size_t)b * CAP2; c = c2; }
    else                   { vals = g_cand3 + (size_t)b * CAP2; c = g_cnt3[b]; }

    double negsum = 0.0;

    if (c <= (unsigned)K) {
        // take everything (all positive candidates; zeros contribute 0)
        float a0 = 0.f, a1 = 0.f, a2 = 0.f, a3 = 0.f;
        unsigned i = tid;
        for (; i + 3u * T2 < c; i += 4u * T2) {
            a0 += vals[i]; a1 += vals[i + T2]; a2 += vals[i + 2u * T2]; a3 += vals[i + 3u * T2];
        }
        for (; i < c; i += T2) a0 += vals[i];
        float acc = (a0 + a1) + (a2 + a3);
        for (int off = 16; off; off >>= 1) acc += __shfl_down_sync(0xffffffffu, acc, off);
        if (lane == 0) red[warp] = (double)acc;
        __syncthreads();
        if (tid == 0) {
#pragma unroll
            for (int i2 = 0; i2 < 32; i2++) negsum += red[i2];
        }
    } else {
        if (tid == 0) { sh_prefix = 0u; sh_krem = K; }
        const unsigned step  = 4u * T2;
        const unsigned cpad4 = ((c + step - 1) / step) * step;  // uniform trips
        for (int r = 0; r < 4; ++r) {
            if (tid < 256) cnt[tid] = 0u;
            __syncthreads();
            const unsigned pfx = sh_prefix;
            const int shift = 24 - 8 * r;
            for (unsigned i0 = tid; i0 < cpad4; i0 += step) {
#pragma unroll
                for (int s = 0; s < 4; ++s) {
                    const unsigned i = i0 + (unsigned)s * T2;
                    const bool valid = (i < c);
                    const unsigned u = valid ? __float_as_uint(vals[i]) : 0u;
                    const bool match = valid && ((r == 0) || ((u >> (32 - 8 * r)) == pfx));
                    const unsigned bin = (u >> shift) & 255u;
                    const unsigned act = __ballot_sync(0xffffffffu, match);
                    if (match) {
                        const unsigned peers = __match_any_sync(act, bin);
                        if (lane == (__ffs(peers) - 1))
                            atomicAdd(&cnt[bin], (unsigned)__popc(peers));
                    }
                }
            }
            __syncthreads();

            // parallel bin selection: suffix-sum over 256 bins (8 steps)
            if (tid < 256) sfx[tid] = cnt[tid];
            __syncthreads();
#pragma unroll
            for (int off = 1; off < 256; off <<= 1) {
                unsigned v = 0;
                if (tid < 256 && tid + off < 256) v = sfx[tid + off];
                __syncthreads();
                if (tid < 256) sfx[tid] += v;
                __syncthreads();
            }
            const unsigned krem_l = (unsigned)sh_krem;     // snapshot before update
            __syncthreads();
            if (tid < 256) {
                // invariant: sfx[0] >= krem_l, so a boundary exists
                const bool sat  = sfx[tid] >= krem_l;
                const bool nsat = (tid + 1 < 256) && (sfx[tid + 1] >= krem_l);
                if (sat && !nsat) {
                    sh_prefix = (sh_prefix << 8) | (unsigned)tid;
                    sh_krem   = (int)(krem_l - ((tid + 1 < 256) ? sfx[tid + 1] : 0u));
                }
            }
            __syncthreads();
        }
        // sum pass: strictly-above sum (bit compare valid for positive floats)
        const unsigned thr = sh_prefix;
        float a0 = 0.f, a1 = 0.f, a2 = 0.f, a3 = 0.f;
        unsigned i = tid;
        for (; i + 3u * T2 < c; i += 4u * T2) {
            float v0 = vals[i], v1 = vals[i + T2], v2 = vals[i + 2u * T2], v3 = vals[i + 3u * T2];
            if (__float_as_uint(v0) > thr) a0 += v0;
            if (__float_as_uint(v1) > thr) a1 += v1;
            if (__float_as_uint(v2) > thr) a2 += v2;
            if (__float_as_uint(v3) > thr) a3 += v3;
        }
        for (; i < c; i += T2) { float v = vals[i]; if (__float_as_uint(v) > thr) a0 += v; }
        float acc = (a0 + a1) + (a2 + a3);
        for (int off = 16; off; off >>= 1) acc += __shfl_down_sync(0xffffffffu, acc, off);
        if (lane == 0) red[warp] = (double)acc;
        __syncthreads();
        if (tid == 0) {
#pragma unroll
            for (int i2 = 0; i2 < 32; i2++) negsum += red[i2];
            negsum += (double)sh_krem * (double)__uint_as_float(thr);  // ties
        }
    }

    if (tid == 0) {
        const float t = ts[b];
        const double per = (t > 0.f)
            ? (g_psum[b] + negsum) / (double)t     // ALPHA = 1
            : 0.0;
        atomicAdd(&g_train, per);

        // reset per-batch scratch for next invocation (after all reads)
        g_cnt2[b] = 0u;
        g_cnt3[b] = 0u;
        g_psum[b] = 0.0;

        __threadfence();                            // publish before ticket
        const unsigned ticket = atomicAdd(&g_done, 1u);
        if (ticket == BATCH - 1) {                  // last batch: fold the scalar
            const double train = g_train / (double)BATCH;
            const double mmean = g_msum / ((double)BATCH * (double)NPER);
            outp[0] = (float)((train + mmean) * 10.0);
            // reset global scratch for next invocation
            g_msum  = 0.0;
            g_train = 0.0;
            g_done  = 0u;
        }
    }
}

// ---------------- launch ----------------------------------------------------
extern "C" void kernel_launch(void* const* d_in, const int* in_sizes, int n_in,
                              void* d_out, int out_size) {
    const float4* y  = (const float4*)d_in[0];
    const float4* o  = (const float4*)d_in[1];
    const float4* w  = (const float4*)d_in[2];
    const float*  ts = (const float*)d_in[3];

    k_hist  <<<BATCH * HBPB, T1>>>(y, o, w, ts);
    k_fused <<<BATCH * BPB, T1>>>(y, o, w);
    k_fb    <<<BATCH * BPB, T1>>>(y, o, w);
    k_topk  <<<BATCH, T2>>>(ts, (float*)d_out);
}